// round 1
// baseline (speedup 1.0000x reference)
#include <cuda_runtime.h>

// Scratch (device globals: no allocations allowed).
__device__ float g_Q[4][64 * 64];   // cayley(u_left), cayley(v_left), cayley(u_right), cayley(v_right)
__device__ float g_M[2][64 * 64];   // m_left [i][l], m_right [j][r]

// ---------------------------------------------------------------------------
// Kernel A: four 64x64 Cayley transforms via Gauss-Jordan (no pivoting; the
// matrix I - A/2 is strongly diagonally dominant for these inputs).
// One block per matrix, 512 threads.
// ---------------------------------------------------------------------------
__global__ void cayley4_kernel(const float* __restrict__ ul,
                               const float* __restrict__ vl,
                               const float* __restrict__ ur,
                               const float* __restrict__ vr) {
    __shared__ float M[64][65];
    __shared__ float B[64][65];
    __shared__ float fac[64];

    const float* src = (blockIdx.x == 0) ? ul
                     : (blockIdx.x == 1) ? vl
                     : (blockIdx.x == 2) ? ur : vr;
    const int tid = threadIdx.x;

    // Build M = I - A/2, B = I + A/2 with A = tril(X,-1) - tril(X,-1)^T
    for (int e = tid; e < 4096; e += blockDim.x) {
        int i = e >> 6, j = e & 63;
        float a = 0.0f;
        if (i > j)      a =  src[i * 64 + j];
        else if (i < j) a = -src[j * 64 + i];
        float h = 0.5f * a;
        float d = (i == j) ? 1.0f : 0.0f;
        M[i][j] = d - h;
        B[i][j] = d + h;
    }
    __syncthreads();

    // Gauss-Jordan elimination (diagonal left unnormalized, fixed at the end).
    for (int k = 0; k < 64; k++) {
        if (tid < 64) {
            fac[tid] = (tid == k) ? 0.0f : M[tid][k] / M[k][k];
        }
        __syncthreads();
        for (int idx = tid; idx < 64 * 128; idx += blockDim.x) {
            int i = idx >> 7, c = idx & 127;
            if (i == k) continue;
            float f = fac[i];
            if (c < 64) M[i][c] -= f * M[k][c];
            else        B[i][c - 64] -= f * B[k][c - 64];
        }
        __syncthreads();
    }

    // Q = diag(M)^{-1} * B
    for (int e = tid; e < 4096; e += blockDim.x) {
        int i = e >> 6, j = e & 63;
        g_Q[blockIdx.x][e] = B[i][j] / M[i][i];
    }
}

// ---------------------------------------------------------------------------
// Kernel B: m = Qu @ (diag[:,None] * Qv).  Block 0 -> m_left, block 1 -> m_right.
// 256 threads, 4x4 register blocking.
// ---------------------------------------------------------------------------
__global__ void combine_kernel(const float* __restrict__ dl,
                               const float* __restrict__ dr) {
    __shared__ float Qu[4096];
    __shared__ float Wv[4096];
    const int b = blockIdx.x;
    const float* qu = g_Q[b * 2 + 0];
    const float* qv = g_Q[b * 2 + 1];
    const float* dg = b ? dr : dl;
    const int tid = threadIdx.x;

    for (int e = tid; e < 4096; e += 256) {
        Qu[e] = qu[e];
        Wv[e] = dg[e >> 6] * qv[e];
    }
    __syncthreads();

    const int ty = tid >> 4, tx = tid & 15;
    const int i0 = ty * 4, c0 = tx * 4;
    float acc[4][4] = {{0.f}};

    #pragma unroll 4
    for (int k = 0; k < 64; k++) {
        float4 bv = *(const float4*)(Wv + k * 64 + c0);
        float a0 = Qu[(i0 + 0) * 64 + k];
        float a1 = Qu[(i0 + 1) * 64 + k];
        float a2 = Qu[(i0 + 2) * 64 + k];
        float a3 = Qu[(i0 + 3) * 64 + k];
        acc[0][0] += a0 * bv.x; acc[0][1] += a0 * bv.y; acc[0][2] += a0 * bv.z; acc[0][3] += a0 * bv.w;
        acc[1][0] += a1 * bv.x; acc[1][1] += a1 * bv.y; acc[1][2] += a1 * bv.z; acc[1][3] += a1 * bv.w;
        acc[2][0] += a2 * bv.x; acc[2][1] += a2 * bv.y; acc[2][2] += a2 * bv.z; acc[2][3] += a2 * bv.w;
        acc[3][0] += a3 * bv.x; acc[3][1] += a3 * bv.y; acc[3][2] += a3 * bv.z; acc[3][3] += a3 * bv.w;
    }
    #pragma unroll
    for (int p = 0; p < 4; p++) {
        *(float4*)(&g_M[b][(i0 + p) * 64 + c0]) =
            make_float4(acc[p][0], acc[p][1], acc[p][2], acc[p][3]);
    }
}

// ---------------------------------------------------------------------------
// Kernel C: per-tile  out = m_left^T @ (x .* diag_scale) @ m_right
// One 64x64 tile per CTA, 256 threads, 4x4 register blocking, two smem GEMMs.
// T buffer is reused for X then Z (saves 16 KB -> 48 KB total, 4 CTAs/SM).
// ---------------------------------------------------------------------------
__global__ void __launch_bounds__(256, 4)
tile_kernel(const float* __restrict__ x,
            const float* __restrict__ dsc,
            float* __restrict__ out) {
    __shared__ float Ml[4096];   // m_left  [i][l]
    __shared__ float Mr[4096];   // m_right [j][r]
    __shared__ float T[4096];    // Xs, then Z

    const int tid = threadIdx.x;
    const size_t base = (size_t)blockIdx.x * 4096;

    for (int e = tid; e < 4096; e += 256) {
        Ml[e] = g_M[0][e];
        Mr[e] = g_M[1][e];
    }
    #pragma unroll
    for (int v = 0; v < 4; v++) {
        int e = (v * 256 + tid) * 4;
        float4 xv = *(const float4*)(x + base + e);
        float4 dv = *(const float4*)(dsc + e);
        *(float4*)(T + e) =
            make_float4(xv.x * dv.x, xv.y * dv.y, xv.z * dv.z, xv.w * dv.w);
    }
    __syncthreads();

    const int ty = tid >> 4, tx = tid & 15;
    const int l0 = ty * 4, r0 = tx * 4;   // r0 doubles as j0 in GEMM1

    // GEMM1: Z[l][j] = sum_i Ml[i][l] * Xs[i][j]
    float acc[4][4] = {{0.f}};
    #pragma unroll 4
    for (int i = 0; i < 64; i++) {
        float4 a = *(const float4*)(Ml + i * 64 + l0);
        float4 b = *(const float4*)(T  + i * 64 + r0);
        acc[0][0] += a.x * b.x; acc[0][1] += a.x * b.y; acc[0][2] += a.x * b.z; acc[0][3] += a.x * b.w;
        acc[1][0] += a.y * b.x; acc[1][1] += a.y * b.y; acc[1][2] += a.y * b.z; acc[1][3] += a.y * b.w;
        acc[2][0] += a.z * b.x; acc[2][1] += a.z * b.y; acc[2][2] += a.z * b.z; acc[2][3] += a.z * b.w;
        acc[3][0] += a.w * b.x; acc[3][1] += a.w * b.y; acc[3][2] += a.w * b.z; acc[3][3] += a.w * b.w;
    }
    __syncthreads();   // all reads of Xs done
    #pragma unroll
    for (int p = 0; p < 4; p++) {
        *(float4*)(T + (l0 + p) * 64 + r0) =
            make_float4(acc[p][0], acc[p][1], acc[p][2], acc[p][3]);
    }
    __syncthreads();

    // GEMM2: O[l][r] = sum_j Z[l][j] * Mr[j][r]
    float acc2[4][4] = {{0.f}};
    #pragma unroll 4
    for (int j = 0; j < 64; j++) {
        float4 b = *(const float4*)(Mr + j * 64 + r0);
        float a0 = T[(l0 + 0) * 64 + j];
        float a1 = T[(l0 + 1) * 64 + j];
        float a2 = T[(l0 + 2) * 64 + j];
        float a3 = T[(l0 + 3) * 64 + j];
        acc2[0][0] += a0 * b.x; acc2[0][1] += a0 * b.y; acc2[0][2] += a0 * b.z; acc2[0][3] += a0 * b.w;
        acc2[1][0] += a1 * b.x; acc2[1][1] += a1 * b.y; acc2[1][2] += a1 * b.z; acc2[1][3] += a1 * b.w;
        acc2[2][0] += a2 * b.x; acc2[2][1] += a2 * b.y; acc2[2][2] += a2 * b.z; acc2[2][3] += a2 * b.w;
        acc2[3][0] += a3 * b.x; acc2[3][1] += a3 * b.y; acc2[3][2] += a3 * b.z; acc2[3][3] += a3 * b.w;
    }
    #pragma unroll
    for (int p = 0; p < 4; p++) {
        *(float4*)(out + base + (l0 + p) * 64 + r0) =
            make_float4(acc2[p][0], acc2[p][1], acc2[p][2], acc2[p][3]);
    }
}

// ---------------------------------------------------------------------------
// Launch
// Inputs (metadata order): x, u_left, v_left, diag_left, u_right, v_right,
//                          diag_right, diag_scale.  Output: float32.
// ---------------------------------------------------------------------------
extern "C" void kernel_launch(void* const* d_in, const int* in_sizes, int n_in,
                              void* d_out, int out_size) {
    const float* x   = (const float*)d_in[0];
    const float* ul  = (const float*)d_in[1];
    const float* vl  = (const float*)d_in[2];
    const float* dl  = (const float*)d_in[3];
    const float* ur  = (const float*)d_in[4];
    const float* vr  = (const float*)d_in[5];
    const float* dr  = (const float*)d_in[6];
    const float* dsc = (const float*)d_in[7];
    float* out = (float*)d_out;

    const int ntile = in_sizes[0] / 4096;   // 8192

    cayley4_kernel<<<4, 512>>>(ul, vl, ur, vr);
    combine_kernel<<<2, 256>>>(dl, dr);
    tile_kernel<<<ntile, 256>>>(x, dsc, out);
}

// round 2
// speedup vs baseline: 1.4238x; 1.4238x over previous
#include <cuda_runtime.h>

// Scratch (device globals: no allocations allowed).
__device__ float g_Q[4][64 * 64];   // cayley(u_left), cayley(v_left), cayley(u_right), cayley(v_right)
__device__ float g_M[2][64 * 64];   // m_left [i][l], m_right [j][r]

// ---------------------------------------------------------------------------
// Packed f32x2 FMA helpers (sm_103a FFMA2 — 2 fp32 FMAs per issue slot).
// ---------------------------------------------------------------------------
__device__ __forceinline__ void ffma2(unsigned long long& d,
                                      unsigned long long a,
                                      unsigned long long b) {
    asm("fma.rn.f32x2 %0, %1, %2, %0;" : "+l"(d) : "l"(a), "l"(b));
}
__device__ __forceinline__ unsigned long long dup2(float v) {
    unsigned long long r;
    asm("mov.b64 %0, {%1, %1};" : "=l"(r) : "r"(__float_as_uint(v)));
    return r;
}

// ---------------------------------------------------------------------------
// In-block 64x64x64 GEMM: D = A @ B (row-major), 256 threads, 4x4 blocking.
// D must be disjoint from A and B. No internal syncs.
// ---------------------------------------------------------------------------
__device__ __forceinline__ void gemm64(float* __restrict__ D,
                                       const float* __restrict__ A,
                                       const float* __restrict__ Bm,
                                       int tid) {
    const int ty = tid >> 4, tx = tid & 15;
    const int i0 = ty * 4, j0 = tx * 4;
    float acc[4][4] = {{0.f}};
    #pragma unroll 4
    for (int k = 0; k < 64; k++) {
        float4 b = *(const float4*)(Bm + k * 64 + j0);
        float a0 = A[(i0 + 0) * 64 + k];
        float a1 = A[(i0 + 1) * 64 + k];
        float a2 = A[(i0 + 2) * 64 + k];
        float a3 = A[(i0 + 3) * 64 + k];
        acc[0][0] += a0 * b.x; acc[0][1] += a0 * b.y; acc[0][2] += a0 * b.z; acc[0][3] += a0 * b.w;
        acc[1][0] += a1 * b.x; acc[1][1] += a1 * b.y; acc[1][2] += a1 * b.z; acc[1][3] += a1 * b.w;
        acc[2][0] += a2 * b.x; acc[2][1] += a2 * b.y; acc[2][2] += a2 * b.z; acc[2][3] += a2 * b.w;
        acc[3][0] += a3 * b.x; acc[3][1] += a3 * b.y; acc[3][2] += a3 * b.z; acc[3][3] += a3 * b.w;
    }
    #pragma unroll
    for (int p = 0; p < 4; p++) {
        *(float4*)(D + (i0 + p) * 64 + j0) =
            make_float4(acc[p][0], acc[p][1], acc[p][2], acc[p][3]);
    }
}

// ---------------------------------------------------------------------------
// Kernel A: four 64x64 Cayley transforms via the product expansion
//   Q = (I-B)^{-1}(I+B) = (I+B)^2 (I+B^2)(I+B^4)(I+B^8)(I+B^16),  B = A/2.
// Exact to ||B||^32 (~1e-25 here; converges for ||B|| < 1).
// 8 in-block GEMMs instead of 64 serialized Gauss-Jordan rounds.
// One block per matrix, 256 threads.
// ---------------------------------------------------------------------------
__global__ void __launch_bounds__(256)
cayley4_kernel(const float* __restrict__ ul, const float* __restrict__ vl,
               const float* __restrict__ ur, const float* __restrict__ vr) {
    __shared__ float b0[4096], b1[4096], b2[4096];

    const float* src = (blockIdx.x == 0) ? ul
                     : (blockIdx.x == 1) ? vl
                     : (blockIdx.x == 2) ? ur : vr;
    const int tid = threadIdx.x;

    // b0 = B = A/2,  A = tril(X,-1) - tril(X,-1)^T
    for (int e = tid; e < 4096; e += 256) {
        int i = e >> 6, j = e & 63;
        float a = 0.0f;
        if (i > j)      a =  src[i * 64 + j];
        else if (i < j) a = -src[j * 64 + i];
        b0[e] = 0.5f * a;
    }
    __syncthreads();

    // b1 = B^2
    gemm64(b1, b0, b0, tid);
    __syncthreads();

    // b2 = P = (I+B)^2 = I + 2B + B^2
    for (int e = tid; e < 4096; e += 256) {
        int i = e >> 6, j = e & 63;
        b2[e] = ((i == j) ? 1.0f : 0.0f) + 2.0f * b0[e] + b1[e];
    }
    __syncthreads();

    // Multiply the remaining factors (I+B^2)(I+B^4)(I+B^8)(I+B^16).
    float* cur = b1;   // holds B^2
    float* P   = b2;
    float* scr = b0;   // B no longer needed
    #pragma unroll 1
    for (int f = 0; f < 4; f++) {
        gemm64(scr, P, cur, tid);       // scr = P * cur
        __syncthreads();
        for (int e = tid; e < 4096; e += 256) P[e] += scr[e];
        __syncthreads();
        if (f < 3) {
            gemm64(scr, cur, cur, tid); // scr = cur^2
            __syncthreads();
            float* t = cur; cur = scr; scr = t;
        }
    }

    for (int e = tid; e < 4096; e += 256) g_Q[blockIdx.x][e] = P[e];
}

// ---------------------------------------------------------------------------
// Kernel B: m = Qu @ (diag[:,None] * Qv).  Block 0 -> m_left, block 1 -> m_right.
// ---------------------------------------------------------------------------
__global__ void __launch_bounds__(256)
combine_kernel(const float* __restrict__ dl, const float* __restrict__ dr) {
    __shared__ float Qu[4096];
    __shared__ float Wv[4096];
    const int b = blockIdx.x;
    const float* qu = g_Q[b * 2 + 0];
    const float* qv = g_Q[b * 2 + 1];
    const float* dg = b ? dr : dl;
    const int tid = threadIdx.x;

    for (int e = tid; e < 4096; e += 256) {
        Qu[e] = qu[e];
        Wv[e] = dg[e >> 6] * qv[e];
    }
    __syncthreads();
    gemm64(g_M[b], Qu, Wv, tid);
}

// ---------------------------------------------------------------------------
// Kernel C: per-tile  out = m_left^T @ (x .* diag_scale) @ m_right
// One 64x64 tile per CTA, 256 threads, 4x4 register blocking done as
// 4x(2-packed) FFMA2 — two fp32 FMAs per fma-pipe issue slot.
// ---------------------------------------------------------------------------
__global__ void __launch_bounds__(256, 4)
tile_kernel(const float* __restrict__ x,
            const float* __restrict__ dsc,
            float* __restrict__ out) {
    __shared__ float Ml[4096];   // m_left  [i][l]
    __shared__ float Mr[4096];   // m_right [j][r]
    __shared__ float T[4096];    // Xs, then Z

    const int tid = threadIdx.x;
    const size_t base = (size_t)blockIdx.x * 4096;

    for (int e = tid; e < 4096; e += 256) {
        Ml[e] = g_M[0][e];
        Mr[e] = g_M[1][e];
    }
    #pragma unroll
    for (int v = 0; v < 4; v++) {
        int e = (v * 256 + tid) * 4;
        float4 xv = *(const float4*)(x + base + e);
        float4 dv = *(const float4*)(dsc + e);
        *(float4*)(T + e) =
            make_float4(xv.x * dv.x, xv.y * dv.y, xv.z * dv.z, xv.w * dv.w);
    }
    __syncthreads();

    const int ty = tid >> 4, tx = tid & 15;
    const int l0 = ty * 4, r0 = tx * 4;   // r0 doubles as j0 in GEMM1

    // GEMM1: Z[l][j] = sum_i Ml[i][l] * Xs[i][j]   (packed pairs along j)
    unsigned long long acc[4][2] = {{0ull, 0ull}, {0ull, 0ull}, {0ull, 0ull}, {0ull, 0ull}};
    #pragma unroll 4
    for (int i = 0; i < 64; i++) {
        float4 a = *(const float4*)(Ml + i * 64 + l0);
        ulonglong2 b = *(const ulonglong2*)(T + i * 64 + r0);
        unsigned long long ap;
        ap = dup2(a.x); ffma2(acc[0][0], ap, b.x); ffma2(acc[0][1], ap, b.y);
        ap = dup2(a.y); ffma2(acc[1][0], ap, b.x); ffma2(acc[1][1], ap, b.y);
        ap = dup2(a.z); ffma2(acc[2][0], ap, b.x); ffma2(acc[2][1], ap, b.y);
        ap = dup2(a.w); ffma2(acc[3][0], ap, b.x); ffma2(acc[3][1], ap, b.y);
    }
    __syncthreads();   // all reads of Xs done
    #pragma unroll
    for (int p = 0; p < 4; p++) {
        ulonglong2 z; z.x = acc[p][0]; z.y = acc[p][1];
        *(ulonglong2*)(T + (l0 + p) * 64 + r0) = z;
    }
    __syncthreads();

    // GEMM2: O[l][r] = sum_j Z[l][j] * Mr[j][r]
    unsigned long long acc2[4][2] = {{0ull, 0ull}, {0ull, 0ull}, {0ull, 0ull}, {0ull, 0ull}};
    #pragma unroll 4
    for (int j = 0; j < 64; j++) {
        ulonglong2 b = *(const ulonglong2*)(Mr + j * 64 + r0);
        unsigned long long ap;
        ap = dup2(T[(l0 + 0) * 64 + j]); ffma2(acc2[0][0], ap, b.x); ffma2(acc2[0][1], ap, b.y);
        ap = dup2(T[(l0 + 1) * 64 + j]); ffma2(acc2[1][0], ap, b.x); ffma2(acc2[1][1], ap, b.y);
        ap = dup2(T[(l0 + 2) * 64 + j]); ffma2(acc2[2][0], ap, b.x); ffma2(acc2[2][1], ap, b.y);
        ap = dup2(T[(l0 + 3) * 64 + j]); ffma2(acc2[3][0], ap, b.x); ffma2(acc2[3][1], ap, b.y);
    }
    #pragma unroll
    for (int p = 0; p < 4; p++) {
        ulonglong2 o; o.x = acc2[p][0]; o.y = acc2[p][1];
        *(ulonglong2*)(out + base + (l0 + p) * 64 + r0) = o;
    }
}

// ---------------------------------------------------------------------------
// Launch.  Inputs (metadata order): x, u_left, v_left, diag_left, u_right,
// v_right, diag_right, diag_scale.  Output: float32.
// ---------------------------------------------------------------------------
extern "C" void kernel_launch(void* const* d_in, const int* in_sizes, int n_in,
                              void* d_out, int out_size) {
    const float* x   = (const float*)d_in[0];
    const float* ul  = (const float*)d_in[1];
    const float* vl  = (const float*)d_in[2];
    const float* dl  = (const float*)d_in[3];
    const float* ur  = (const float*)d_in[4];
    const float* vr  = (const float*)d_in[5];
    const float* dr  = (const float*)d_in[6];
    const float* dsc = (const float*)d_in[7];
    float* out = (float*)d_out;

    const int ntile = in_sizes[0] / 4096;   // 8192

    cayley4_kernel<<<4, 256>>>(ul, vl, ur, vr);
    combine_kernel<<<2, 256>>>(dl, dr);
    tile_kernel<<<ntile, 256>>>(x, dsc, out);
}

// round 4
// speedup vs baseline: 2.0178x; 1.4172x over previous
#include <cuda_runtime.h>
#include <cuda_bf16.h>
#include <cstdint>

// ---------------------------------------------------------------------------
// Scratch (device globals; allocations are forbidden).
// ---------------------------------------------------------------------------
__device__ float g_Q[4][4096];   // cayley(u_left), cayley(v_left), cayley(u_right), cayley(v_right)
// Constant operand images, bf16 split, row-major 64x64 (padded on copy to smem):
//   g_mrt_* : Mr^T  [r][j]   (B of GEMM1, n-major rows, k contiguous)
//   g_mlt_* : Ml^T  [l][i]   (A of GEMM2, m-major rows, k contiguous)
__device__ __align__(16) __nv_bfloat16 g_mrt_hi[4096], g_mrt_lo[4096];
__device__ __align__(16) __nv_bfloat16 g_mlt_hi[4096], g_mlt_lo[4096];

// ---------------------------------------------------------------------------
// Helpers
// ---------------------------------------------------------------------------
__device__ __forceinline__ void split_bf(float v, __nv_bfloat16& hi, __nv_bfloat16& lo) {
    hi = __float2bfloat16_rn(v);
    lo = __float2bfloat16_rn(v - __bfloat162float(hi));
}
__device__ __forceinline__ uint32_t pack2(__nv_bfloat16 a, __nv_bfloat16 b) {
    return (uint32_t)__bfloat16_as_ushort(a) | ((uint32_t)__bfloat16_as_ushort(b) << 16);
}

// mma.sync m16n8k16, bf16 x bf16 -> f32 accumulate (baseline PTX, sm_80+).
__device__ __forceinline__ void mma_bf16(float c[4], const uint32_t a[4],
                                         uint32_t b0, uint32_t b1) {
    asm volatile(
        "mma.sync.aligned.m16n8k16.row.col.f32.bf16.bf16.f32 "
        "{%0,%1,%2,%3}, {%4,%5,%6,%7}, {%8,%9}, {%0,%1,%2,%3};"
        : "+f"(c[0]), "+f"(c[1]), "+f"(c[2]), "+f"(c[3])
        : "r"(a[0]), "r"(a[1]), "r"(a[2]), "r"(a[3]), "r"(b0), "r"(b1));
}

// ---------------------------------------------------------------------------
// In-block 64^3 GEMM for setup (512 / 256 thread variants).
// ---------------------------------------------------------------------------
__device__ __forceinline__ void gemm64_512(float* __restrict__ D,
                                           const float* __restrict__ A,
                                           const float* __restrict__ Bm, int tid) {
    const int i0 = (tid >> 4) * 2, j0 = (tid & 15) * 4;
    float acc[2][4] = {{0.f}};
    #pragma unroll 4
    for (int k = 0; k < 64; k++) {
        float4 b = *(const float4*)(Bm + k * 64 + j0);
        float a0 = A[(i0 + 0) * 64 + k];
        float a1 = A[(i0 + 1) * 64 + k];
        acc[0][0] += a0 * b.x; acc[0][1] += a0 * b.y; acc[0][2] += a0 * b.z; acc[0][3] += a0 * b.w;
        acc[1][0] += a1 * b.x; acc[1][1] += a1 * b.y; acc[1][2] += a1 * b.z; acc[1][3] += a1 * b.w;
    }
    #pragma unroll
    for (int p = 0; p < 2; p++)
        *(float4*)(D + (i0 + p) * 64 + j0) =
            make_float4(acc[p][0], acc[p][1], acc[p][2], acc[p][3]);
}

__device__ __forceinline__ void gemm64_256(float* __restrict__ D,
                                           const float* __restrict__ A,
                                           const float* __restrict__ Bm, int tid) {
    const int i0 = (tid >> 4) * 4, j0 = (tid & 15) * 4;
    float acc[4][4] = {{0.f}};
    #pragma unroll 4
    for (int k = 0; k < 64; k++) {
        float4 b = *(const float4*)(Bm + k * 64 + j0);
        float a0 = A[(i0 + 0) * 64 + k];
        float a1 = A[(i0 + 1) * 64 + k];
        float a2 = A[(i0 + 2) * 64 + k];
        float a3 = A[(i0 + 3) * 64 + k];
        acc[0][0] += a0 * b.x; acc[0][1] += a0 * b.y; acc[0][2] += a0 * b.z; acc[0][3] += a0 * b.w;
        acc[1][0] += a1 * b.x; acc[1][1] += a1 * b.y; acc[1][2] += a1 * b.z; acc[1][3] += a1 * b.w;
        acc[2][0] += a2 * b.x; acc[2][1] += a2 * b.y; acc[2][2] += a2 * b.z; acc[2][3] += a2 * b.w;
        acc[3][0] += a3 * b.x; acc[3][1] += a3 * b.y; acc[3][2] += a3 * b.z; acc[3][3] += a3 * b.w;
    }
    #pragma unroll
    for (int p = 0; p < 4; p++)
        *(float4*)(D + (i0 + p) * 64 + j0) =
            make_float4(acc[p][0], acc[p][1], acc[p][2], acc[p][3]);
}

// ---------------------------------------------------------------------------
// Kernel A: cayley via product expansion:
//   Q = (I+B)^2 (I+B^2)(I+B^4)(I+B^8),  B = A/2.  trunc err ~||B||^16 ~ 1e-13.
// ---------------------------------------------------------------------------
__global__ void __launch_bounds__(512)
cayley4_kernel(const float* __restrict__ ul, const float* __restrict__ vl,
               const float* __restrict__ ur, const float* __restrict__ vr) {
    __shared__ float b0[4096], b1[4096], b2[4096];
    const float* src = (blockIdx.x == 0) ? ul : (blockIdx.x == 1) ? vl
                     : (blockIdx.x == 2) ? ur : vr;
    const int tid = threadIdx.x;

    for (int e = tid; e < 4096; e += 512) {
        int i = e >> 6, j = e & 63;
        float a = 0.0f;
        if (i > j)      a =  src[i * 64 + j];
        else if (i < j) a = -src[j * 64 + i];
        b0[e] = 0.5f * a;                        // B
    }
    __syncthreads();
    gemm64_512(b1, b0, b0, tid);                 // b1 = B^2
    __syncthreads();
    for (int e = tid; e < 4096; e += 512) {
        int i = e >> 6, j = e & 63;
        b2[e] = ((i == j) ? 1.0f : 0.0f) + 2.0f * b0[e] + b1[e];   // P=(I+B)^2
    }
    __syncthreads();
    gemm64_512(b0, b2, b1, tid); __syncthreads();        // P *= (I+B^2)
    for (int e = tid; e < 4096; e += 512) b2[e] += b0[e];
    __syncthreads();
    gemm64_512(b0, b1, b1, tid); __syncthreads();        // b0 = B^4
    gemm64_512(b1, b2, b0, tid); __syncthreads();        // P *= (I+B^4)
    for (int e = tid; e < 4096; e += 512) b2[e] += b1[e];
    __syncthreads();
    gemm64_512(b1, b0, b0, tid); __syncthreads();        // b1 = B^8
    gemm64_512(b0, b2, b1, tid); __syncthreads();        // P *= (I+B^8)
    for (int e = tid; e < 4096; e += 512) g_Q[blockIdx.x][e] = b2[e] + b0[e];
}

// ---------------------------------------------------------------------------
// Kernel B: m = Qu @ (diag * Qv); emit transposed bf16 split images.
//   block 0: m_left  -> g_mlt_* [l][i] = m_left[i][l]
//   block 1: m_right -> g_mrt_* [r][j] = m_right[j][r]
// ---------------------------------------------------------------------------
__global__ void __launch_bounds__(256)
combine_kernel(const float* __restrict__ dl, const float* __restrict__ dr) {
    __shared__ float Qu[4096], Wv[4096], D[4096];
    const int b = blockIdx.x;
    const float* qu = g_Q[b * 2 + 0];
    const float* qv = g_Q[b * 2 + 1];
    const float* dg = b ? dr : dl;
    const int tid = threadIdx.x;

    for (int e = tid; e < 4096; e += 256) {
        Qu[e] = qu[e];
        Wv[e] = dg[e >> 6] * qv[e];
    }
    __syncthreads();
    gemm64_256(D, Qu, Wv, tid);      // D = m (row-major [row][col])
    __syncthreads();

    __nv_bfloat16* hi = b ? g_mrt_hi : g_mlt_hi;
    __nv_bfloat16* lo = b ? g_mrt_lo : g_mlt_lo;
    for (int e = tid; e < 4096; e += 256) {
        int t = e >> 6, s = e & 63;          // out[t][s] = D[s][t]
        __nv_bfloat16 h, l;
        split_bf(D[s * 64 + t], h, l);
        hi[e] = h; lo[e] = l;
    }
}

// ---------------------------------------------------------------------------
// Kernel C: mma.sync path.  CTA = 8 warps, 4 tiles.
// Per tile: GEMM1 C1 = Xs*Mr (warp w owns r in [8w,8w+8)), C1^T restaged
// hi/lo into warp-private smem rows, GEMM2 O = Ml^T*C1 (same r slab).
// 3 split chains per GEMM. smem rows padded to 72 bf16 (conflict-free frags).
// ---------------------------------------------------------------------------
#define PADB   144                 // 72 bf16 per row
#define MATB   (64 * PADB)         // 9216 B
#define MRT_HI 0
#define MRT_LO (MATB)
#define MLT_HI (2 * MATB)
#define MLT_LO (3 * MATB)
#define XHI    (4 * MATB)
#define XLO    (5 * MATB)
#define C1_HI  (6 * MATB)
#define C1_LO  (7 * MATB)
#define SMEM_SZ (8 * MATB)         // 73728 B

__global__ void __launch_bounds__(256, 2)
tile_kernel(const float* __restrict__ x,
            const float* __restrict__ dsc,
            float* __restrict__ out) {
    extern __shared__ char sm[];
    const int tid = threadIdx.x;
    const int wid = tid >> 5, lane = tid & 31;
    const int g = lane >> 2, tg = lane & 3;

    // Constants -> smem with pad re-stride (32 u32-words per 64-bf16 row).
    for (int q = tid; q < 2048; q += 256) {
        const int row = q >> 5, cw = q & 31;
        const int d = row * 36 + cw;
        ((uint32_t*)(sm + MRT_HI))[d] = ((const uint32_t*)g_mrt_hi)[q];
        ((uint32_t*)(sm + MRT_LO))[d] = ((const uint32_t*)g_mrt_lo)[q];
        ((uint32_t*)(sm + MLT_HI))[d] = ((const uint32_t*)g_mlt_hi)[q];
        ((uint32_t*)(sm + MLT_LO))[d] = ((const uint32_t*)g_mlt_lo)[q];
    }

    // diag_scale staged in registers (same elements every tile).
    float4 dreg[4];
    #pragma unroll
    for (int v = 0; v < 4; v++) dreg[v] = ((const float4*)dsc)[v * 256 + tid];

    const int boff = (wid * 8 + g) * PADB + tg * 4;   // B-frag base (n-row, k-col bytes)
    const int aoff = g * PADB + tg * 4;               // A-frag base within m-tile

    for (int it = 0; it < 4; it++) {
        const size_t tbase = ((size_t)blockIdx.x * 4 + it) * 4096;
        __syncthreads();   // protect X buffer from previous iteration's readers

        // Stage X: scale, split, smem row-major [i][j] padded.
        const float4* xt = (const float4*)(x + tbase);
        #pragma unroll
        for (int v = 0; v < 4; v++) {
            const int idx = v * 256 + tid;
            float4 xv = xt[idx];
            const float4 dv = dreg[v];
            float s0 = xv.x * dv.x, s1 = xv.y * dv.y, s2 = xv.z * dv.z, s3 = xv.w * dv.w;
            __nv_bfloat16 h0, l0, h1, l1, h2, l2, h3, l3;
            split_bf(s0, h0, l0); split_bf(s1, h1, l1);
            split_bf(s2, h2, l2); split_bf(s3, h3, l3);
            const int e = idx * 4, i = e >> 6, j = e & 63;
            const int ob = i * PADB + j * 2;
            *(uint2*)(sm + XHI + ob) = make_uint2(pack2(h0, h1), pack2(h2, h3));
            *(uint2*)(sm + XLO + ob) = make_uint2(pack2(l0, l1), pack2(l2, l3));
        }
        __syncthreads();

        // ---- GEMM1: C1[i][r] = sum_j Xs[i][j] * Mr[j][r] ----
        float acc1[4][4] = {{0.f}};
        #pragma unroll
        for (int kt = 0; kt < 4; kt++) {
            const int kb = kt * 32;
            const uint32_t bh0 = *(const uint32_t*)(sm + MRT_HI + boff + kb);
            const uint32_t bh1 = *(const uint32_t*)(sm + MRT_HI + boff + kb + 16);
            const uint32_t bl0 = *(const uint32_t*)(sm + MRT_LO + boff + kb);
            const uint32_t bl1 = *(const uint32_t*)(sm + MRT_LO + boff + kb + 16);
            #pragma unroll
            for (int mt = 0; mt < 4; mt++) {
                const int ab = mt * 16 * PADB + aoff + kb;
                uint32_t ah[4] = {
                    *(const uint32_t*)(sm + XHI + ab),
                    *(const uint32_t*)(sm + XHI + ab + 8 * PADB),
                    *(const uint32_t*)(sm + XHI + ab + 16),
                    *(const uint32_t*)(sm + XHI + ab + 8 * PADB + 16) };
                uint32_t al[4] = {
                    *(const uint32_t*)(sm + XLO + ab),
                    *(const uint32_t*)(sm + XLO + ab + 8 * PADB),
                    *(const uint32_t*)(sm + XLO + ab + 16),
                    *(const uint32_t*)(sm + XLO + ab + 8 * PADB + 16) };
                mma_bf16(acc1[mt], ah, bh0, bh1);
                mma_bf16(acc1[mt], ah, bl0, bl1);
                mma_bf16(acc1[mt], al, bh0, bh1);
            }
        }

        // Restage C1^T (warp-private rows r in [8w, 8w+8)), split hi/lo.
        {
            const int r0 = wid * 8 + tg * 2;
            #pragma unroll
            for (int mt = 0; mt < 4; mt++) {
                const int i0 = mt * 16 + g;
                #pragma unroll
                for (int q = 0; q < 4; q++) {
                    const int rr = r0 + (q & 1);
                    const int ii = i0 + (q >> 1) * 8;
                    __nv_bfloat16 h, l;
                    split_bf(acc1[mt][q], h, l);
                    const int ob = rr * PADB + ii * 2;
                    *(__nv_bfloat16*)(sm + C1_HI + ob) = h;
                    *(__nv_bfloat16*)(sm + C1_LO + ob) = l;
                }
            }
        }
        __syncwarp();

        // ---- GEMM2: O[l][r] = sum_i Mlt[l][i] * C1[i][r] ----
        float acc2[4][4] = {{0.f}};
        #pragma unroll
        for (int kt = 0; kt < 4; kt++) {
            const int kb = kt * 32;
            const uint32_t bh0 = *(const uint32_t*)(sm + C1_HI + boff + kb);
            const uint32_t bh1 = *(const uint32_t*)(sm + C1_HI + boff + kb + 16);
            const uint32_t bl0 = *(const uint32_t*)(sm + C1_LO + boff + kb);
            const uint32_t bl1 = *(const uint32_t*)(sm + C1_LO + boff + kb + 16);
            #pragma unroll
            for (int mt = 0; mt < 4; mt++) {
                const int ab = mt * 16 * PADB + aoff + kb;
                uint32_t ah[4] = {
                    *(const uint32_t*)(sm + MLT_HI + ab),
                    *(const uint32_t*)(sm + MLT_HI + ab + 8 * PADB),
                    *(const uint32_t*)(sm + MLT_HI + ab + 16),
                    *(const uint32_t*)(sm + MLT_HI + ab + 8 * PADB + 16) };
                uint32_t al[4] = {
                    *(const uint32_t*)(sm + MLT_LO + ab),
                    *(const uint32_t*)(sm + MLT_LO + ab + 8 * PADB),
                    *(const uint32_t*)(sm + MLT_LO + ab + 16),
                    *(const uint32_t*)(sm + MLT_LO + ab + 8 * PADB + 16) };
                mma_bf16(acc2[mt], ah, bh0, bh1);
                mma_bf16(acc2[mt], ah, bl0, bl1);
                mma_bf16(acc2[mt], al, bh0, bh1);
            }
        }

        // Store O to gmem.
        {
            float* ob = out + tbase;
            const int r0 = wid * 8 + tg * 2;
            #pragma unroll
            for (int mt = 0; mt < 4; mt++) {
                const int l0 = mt * 16 + g;
                *(float2*)(ob + l0 * 64 + r0)       = make_float2(acc2[mt][0], acc2[mt][1]);
                *(float2*)(ob + (l0 + 8) * 64 + r0) = make_float2(acc2[mt][2], acc2[mt][3]);
            }
        }
    }
}

// ---------------------------------------------------------------------------
// Launch.  Inputs: x, u_left, v_left, diag_left, u_right, v_right, diag_right,
// diag_scale.  Output float32.
// ---------------------------------------------------------------------------
extern "C" void kernel_launch(void* const* d_in, const int* in_sizes, int n_in,
                              void* d_out, int out_size) {
    const float* x   = (const float*)d_in[0];
    const float* ul  = (const float*)d_in[1];
    const float* vl  = (const float*)d_in[2];
    const float* dl  = (const float*)d_in[3];
    const float* ur  = (const float*)d_in[4];
    const float* vr  = (const float*)d_in[5];
    const float* dr  = (const float*)d_in[6];
    const float* dsc = (const float*)d_in[7];
    float* out = (float*)d_out;

    const int ntile = in_sizes[0] / 4096;   // 8192

    cudaFuncSetAttribute(tile_kernel, cudaFuncAttributeMaxDynamicSharedMemorySize, SMEM_SZ);

    cayley4_kernel<<<4, 512>>>(ul, vl, ur, vr);
    combine_kernel<<<2, 256>>>(dl, dr);
    tile_kernel<<<ntile / 4, 256, SMEM_SZ>>>(x, dsc, out);
}

// round 6
// speedup vs baseline: 2.4674x; 1.2228x over previous
#include <cuda_runtime.h>
#include <cuda_bf16.h>
#include <cstdint>

// ---------------------------------------------------------------------------
// Scratch (device globals; allocations are forbidden).
// ---------------------------------------------------------------------------
__device__ float g_Q[4][4096];
// Constant operand images, bf16 split, row-major 64x64:
//   g_mrt_* : Mr^T [r][j]  (B of GEMM1)
//   g_mlt_* : Ml^T [l][i]  (A of GEMM2)
__device__ __align__(16) __nv_bfloat16 g_mrt_hi[4096], g_mrt_lo[4096];
__device__ __align__(16) __nv_bfloat16 g_mlt_hi[4096], g_mlt_lo[4096];

// ---------------------------------------------------------------------------
// Helpers
// ---------------------------------------------------------------------------
__device__ __forceinline__ void ffma2p(unsigned long long& d,
                                       unsigned long long a,
                                       unsigned long long b) {
    asm("fma.rn.f32x2 %0, %1, %2, %0;" : "+l"(d) : "l"(a), "l"(b));
}
__device__ __forceinline__ unsigned long long dup2(float v) {
    unsigned long long r;
    asm("mov.b64 %0, {%1, %1};" : "=l"(r) : "r"(__float_as_uint(v)));
    return r;
}
// paired f32 -> bf16x2 (lo half = a, hi half = b)
__device__ __forceinline__ uint32_t cvt_bf2(float a, float b) {
    uint32_t r;
    asm("cvt.rn.satfinite.bf16x2.f32 %0, %1, %2;" : "=r"(r) : "f"(b), "f"(a));
    return r;
}

// mma.sync m16n8k16 bf16 -> f32 (baseline PTX, legal at sm_103).
__device__ __forceinline__ void mma_bf16(float c[4], const uint32_t a[4],
                                         uint32_t b0, uint32_t b1) {
    asm volatile(
        "mma.sync.aligned.m16n8k16.row.col.f32.bf16.bf16.f32 "
        "{%0,%1,%2,%3}, {%4,%5,%6,%7}, {%8,%9}, {%0,%1,%2,%3};"
        : "+f"(c[0]), "+f"(c[1]), "+f"(c[2]), "+f"(c[3])
        : "r"(a[0]), "r"(a[1]), "r"(a[2]), "r"(a[3]), "r"(b0), "r"(b1));
}

// ---------------------------------------------------------------------------
// In-block 64^3 GEMM, 512 threads, 2x4 blocking with packed FFMA2.
// ---------------------------------------------------------------------------
__device__ __forceinline__ void gemm64p(float* __restrict__ D,
                                        const float* __restrict__ A,
                                        const float* __restrict__ Bm, int tid) {
    const int i0 = (tid >> 4) * 2, j0 = (tid & 15) * 4;
    unsigned long long acc[2][2] = {{0ull, 0ull}, {0ull, 0ull}};
    #pragma unroll 4
    for (int k = 0; k < 64; k++) {
        ulonglong2 b = *(const ulonglong2*)(Bm + k * 64 + j0);
        unsigned long long a0 = dup2(A[(i0 + 0) * 64 + k]);
        unsigned long long a1 = dup2(A[(i0 + 1) * 64 + k]);
        ffma2p(acc[0][0], a0, b.x); ffma2p(acc[0][1], a0, b.y);
        ffma2p(acc[1][0], a1, b.x); ffma2p(acc[1][1], a1, b.y);
    }
    #pragma unroll
    for (int p = 0; p < 2; p++) {
        ulonglong2 o; o.x = acc[p][0]; o.y = acc[p][1];
        *(ulonglong2*)(D + (i0 + p) * 64 + j0) = o;
    }
}

// ---------------------------------------------------------------------------
// Kernel A: cayley via truncated product: Q = (I+B)^2 (I+B^2)(I+B^4),
// covers B^0..B^7 exactly; trunc err ~||B||^8 ~ 3e-7.  4 GEMMs.
// ---------------------------------------------------------------------------
__global__ void __launch_bounds__(512)
cayley4_kernel(const float* __restrict__ ul, const float* __restrict__ vl,
               const float* __restrict__ ur, const float* __restrict__ vr) {
    __shared__ float b0[4096], b1[4096], b2[4096];
    const float* src = (blockIdx.x == 0) ? ul : (blockIdx.x == 1) ? vl
                     : (blockIdx.x == 2) ? ur : vr;
    const int tid = threadIdx.x;

    for (int e = tid; e < 4096; e += 512) {
        int i = e >> 6, j = e & 63;
        float a = 0.0f;
        if (i > j)      a =  src[i * 64 + j];
        else if (i < j) a = -src[j * 64 + i];
        b0[e] = 0.5f * a;                         // B
    }
    __syncthreads();
    gemm64p(b1, b0, b0, tid);                     // b1 = B^2
    __syncthreads();
    for (int e = tid; e < 4096; e += 512) {
        int i = e >> 6, j = e & 63;
        b2[e] = ((i == j) ? 1.0f : 0.0f) + 2.0f * b0[e] + b1[e];   // P = (I+B)^2
    }
    __syncthreads();
    gemm64p(b0, b2, b1, tid); __syncthreads();    // b0 = P*B^2
    for (int e = tid; e < 4096; e += 512) b2[e] += b0[e];          // P *= (I+B^2)
    __syncthreads();
    gemm64p(b0, b1, b1, tid); __syncthreads();    // b0 = B^4
    gemm64p(b1, b2, b0, tid); __syncthreads();    // b1 = P*B^4
    for (int e = tid; e < 4096; e += 512) g_Q[blockIdx.x][e] = b2[e] + b1[e];
}

// ---------------------------------------------------------------------------
// Kernel B: m = Qu @ (diag * Qv); emit transposed bf16 split images.
// ---------------------------------------------------------------------------
__global__ void __launch_bounds__(512)
combine_kernel(const float* __restrict__ dl, const float* __restrict__ dr) {
    __shared__ float Qu[4096], Wv[4096], D[4096];
    const int b = blockIdx.x;
    const float* qu = g_Q[b * 2 + 0];
    const float* qv = g_Q[b * 2 + 1];
    const float* dg = b ? dr : dl;
    const int tid = threadIdx.x;

    for (int e = tid; e < 4096; e += 512) {
        Qu[e] = qu[e];
        Wv[e] = dg[e >> 6] * qv[e];
    }
    __syncthreads();
    gemm64p(D, Qu, Wv, tid);
    __syncthreads();

    __nv_bfloat16* hi = b ? g_mrt_hi : g_mlt_hi;
    __nv_bfloat16* lo = b ? g_mrt_lo : g_mlt_lo;
    for (int e = tid; e < 4096; e += 512) {
        int t = e >> 6, s = e & 63;               // out[t][s] = D[s][t]
        float v = D[s * 64 + t];
        __nv_bfloat16 h = __float2bfloat16_rn(v);
        float hf = __uint_as_float((uint32_t)__bfloat16_as_ushort(h) << 16);
        hi[e] = h;
        lo[e] = __float2bfloat16_rn(v - hf);
    }
}

// ---------------------------------------------------------------------------
// Kernel C: mma.sync path.  CTA = 8 warps, 4 tiles in 2 passes.
// Per pass 2 tiles are staged; warp w: tile tt = w>>2, n-slab s = w&3
// (r in [16s, 16s+16)).  GEMM1 C1 = Xs*Mr, warp-private C1^T restage,
// GEMM2 O = Ml^T*C1.  3 split chains each.  Rows padded to 72 bf16.
// ---------------------------------------------------------------------------
#define PADB   144                 // bytes per 64-bf16 row (72 bf16)
#define MATB   (64 * PADB)         // 9216
#define MRT_HI 0
#define MRT_LO (MATB)
#define MLT_HI (2 * MATB)
#define MLT_LO (3 * MATB)
#define XBASE  (4 * MATB)          // X images: tile tt -> XBASE + tt*2*MATB (+MATB lo)
#define C1BASE (8 * MATB)          // C1 images: tile tt -> C1BASE + tt*2*MATB
#define SMEM_SZ (12 * MATB)        // 110592

__global__ void __launch_bounds__(256, 2)
tile_kernel(const float* __restrict__ x,
            const float* __restrict__ dsc,
            float* __restrict__ out) {
    extern __shared__ char sm[];
    const int tid = threadIdx.x;
    const int wid = tid >> 5, lane = tid & 31;
    const int g = lane >> 2, tg = lane & 3;
    const int tt = wid >> 2, s = wid & 3;

    // Constants -> smem with pad re-stride.
    for (int q = tid; q < 2048; q += 256) {
        const int row = q >> 5, cw = q & 31;
        const int d = row * 36 + cw;
        ((uint32_t*)(sm + MRT_HI))[d] = ((const uint32_t*)g_mrt_hi)[q];
        ((uint32_t*)(sm + MRT_LO))[d] = ((const uint32_t*)g_mrt_lo)[q];
        ((uint32_t*)(sm + MLT_HI))[d] = ((const uint32_t*)g_mlt_hi)[q];
        ((uint32_t*)(sm + MLT_LO))[d] = ((const uint32_t*)g_mlt_lo)[q];
    }

    float4 dreg[4];
    #pragma unroll
    for (int v = 0; v < 4; v++) dreg[v] = ((const float4*)dsc)[v * 256 + tid];

    const int xhi = XBASE + tt * 2 * MATB, xlo = xhi + MATB;
    const int chi = C1BASE + tt * 2 * MATB, clo = chi + MATB;
    const int aoff = g * PADB + tg * 4;

    for (int pass = 0; pass < 2; pass++) {
        const size_t pbase = ((size_t)blockIdx.x * 4 + pass * 2) * 4096;
        __syncthreads();   // X/C1 buffers free from previous pass

        // Stage both tiles' X: scale, paired split, padded row-major.
        #pragma unroll
        for (int st = 0; st < 2; st++) {
            const int xh = XBASE + st * 2 * MATB, xl = xh + MATB;
            const float4* xt = (const float4*)(x + pbase + st * 4096);
            #pragma unroll
            for (int v = 0; v < 4; v++) {
                const int idx = v * 256 + tid;
                float4 xv = xt[idx];
                const float4 dv = dreg[v];
                float s0 = xv.x * dv.x, s1 = xv.y * dv.y;
                float s2 = xv.z * dv.z, s3 = xv.w * dv.w;
                uint32_t h01 = cvt_bf2(s0, s1), h23 = cvt_bf2(s2, s3);
                float l0 = s0 - __uint_as_float(h01 << 16);
                float l1 = s1 - __uint_as_float(h01 & 0xFFFF0000u);
                float l2 = s2 - __uint_as_float(h23 << 16);
                float l3 = s3 - __uint_as_float(h23 & 0xFFFF0000u);
                const int e = idx * 4, i = e >> 6, j = e & 63;
                const int ob = i * PADB + j * 2;
                *(uint2*)(sm + xh + ob) = make_uint2(h01, h23);
                *(uint2*)(sm + xl + ob) = make_uint2(cvt_bf2(l0, l1), cvt_bf2(l2, l3));
            }
        }
        __syncthreads();

        // ---- GEMM1: C1[i][r] = sum_j Xs[i][j] * Mr[j][r] ----
        float acc1[2][4][4] = {};
        #pragma unroll
        for (int kt = 0; kt < 4; kt++) {
            const int kb = kt * 32;
            uint32_t bh0[2], bh1[2], bl0[2], bl1[2];
            #pragma unroll
            for (int nt = 0; nt < 2; nt++) {
                const int br = (s * 16 + nt * 8 + g) * PADB + tg * 4 + kb;
                bh0[nt] = *(const uint32_t*)(sm + MRT_HI + br);
                bh1[nt] = *(const uint32_t*)(sm + MRT_HI + br + 16);
                bl0[nt] = *(const uint32_t*)(sm + MRT_LO + br);
                bl1[nt] = *(const uint32_t*)(sm + MRT_LO + br + 16);
            }
            #pragma unroll
            for (int mt = 0; mt < 4; mt++) {
                const int ab = mt * 16 * PADB + aoff + kb;
                uint32_t ah[4] = {
                    *(const uint32_t*)(sm + xhi + ab),
                    *(const uint32_t*)(sm + xhi + ab + 8 * PADB),
                    *(const uint32_t*)(sm + xhi + ab + 16),
                    *(const uint32_t*)(sm + xhi + ab + 8 * PADB + 16) };
                uint32_t al[4] = {
                    *(const uint32_t*)(sm + xlo + ab),
                    *(const uint32_t*)(sm + xlo + ab + 8 * PADB),
                    *(const uint32_t*)(sm + xlo + ab + 16),
                    *(const uint32_t*)(sm + xlo + ab + 8 * PADB + 16) };
                #pragma unroll
                for (int nt = 0; nt < 2; nt++) {
                    mma_bf16(acc1[nt][mt], ah, bh0[nt], bh1[nt]);
                    mma_bf16(acc1[nt][mt], ah, bl0[nt], bl1[nt]);
                    mma_bf16(acc1[nt][mt], al, bh0[nt], bh1[nt]);
                }
            }
        }

        // Restage C1^T rows (warp-private r in [16s, 16s+16)), split hi/lo.
        #pragma unroll
        for (int nt = 0; nt < 2; nt++) {
            #pragma unroll
            for (int mt = 0; mt < 4; mt++) {
                #pragma unroll
                for (int q = 0; q < 4; q++) {
                    const int rr = s * 16 + nt * 8 + tg * 2 + (q & 1);
                    const int ii = mt * 16 + g + (q >> 1) * 8;
                    const float v = acc1[nt][mt][q];
                    __nv_bfloat16 h = __float2bfloat16_rn(v);
                    float hf = __uint_as_float((uint32_t)__bfloat16_as_ushort(h) << 16);
                    const int ob = rr * PADB + ii * 2;
                    *(__nv_bfloat16*)(sm + chi + ob) = h;
                    *(__nv_bfloat16*)(sm + clo + ob) = __float2bfloat16_rn(v - hf);
                }
            }
        }
        __syncwarp();

        // ---- GEMM2: O[l][r] = sum_i Mlt[l][i] * C1[i][r] ----
        float acc2[2][4][4] = {};
        #pragma unroll
        for (int kt = 0; kt < 4; kt++) {
            const int kb = kt * 32;
            uint32_t bh0[2], bh1[2], bl0[2], bl1[2];
            #pragma unroll
            for (int nt = 0; nt < 2; nt++) {
                const int br = (s * 16 + nt * 8 + g) * PADB + tg * 4 + kb;
                bh0[nt] = *(const uint32_t*)(sm + chi + br);
                bh1[nt] = *(const uint32_t*)(sm + chi + br + 16);
                bl0[nt] = *(const uint32_t*)(sm + clo + br);
                bl1[nt] = *(const uint32_t*)(sm + clo + br + 16);
            }
            #pragma unroll
            for (int mt = 0; mt < 4; mt++) {
                const int ab = mt * 16 * PADB + aoff + kb;
                uint32_t ah[4] = {
                    *(const uint32_t*)(sm + MLT_HI + ab),
                    *(const uint32_t*)(sm + MLT_HI + ab + 8 * PADB),
                    *(const uint32_t*)(sm + MLT_HI + ab + 16),
                    *(const uint32_t*)(sm + MLT_HI + ab + 8 * PADB + 16) };
                uint32_t al[4] = {
                    *(const uint32_t*)(sm + MLT_LO + ab),
                    *(const uint32_t*)(sm + MLT_LO + ab + 8 * PADB),
                    *(const uint32_t*)(sm + MLT_LO + ab + 16),
                    *(const uint32_t*)(sm + MLT_LO + ab + 8 * PADB + 16) };
                #pragma unroll
                for (int nt = 0; nt < 2; nt++) {
                    mma_bf16(acc2[nt][mt], ah, bh0[nt], bh1[nt]);
                    mma_bf16(acc2[nt][mt], ah, bl0[nt], bl1[nt]);
                    mma_bf16(acc2[nt][mt], al, bh0[nt], bh1[nt]);
                }
            }
        }

        // Store O.
        {
            float* ob = out + pbase + tt * 4096;
            #pragma unroll
            for (int nt = 0; nt < 2; nt++) {
                const int r0 = s * 16 + nt * 8 + tg * 2;
                #pragma unroll
                for (int mt = 0; mt < 4; mt++) {
                    const int l0 = mt * 16 + g;
                    *(float2*)(ob + l0 * 64 + r0) =
                        make_float2(acc2[nt][mt][0], acc2[nt][mt][1]);
                    *(float2*)(ob + (l0 + 8) * 64 + r0) =
                        make_float2(acc2[nt][mt][2], acc2[nt][mt][3]);
                }
            }
        }
    }
}

// ---------------------------------------------------------------------------
// Launch.  Inputs: x, u_left, v_left, diag_left, u_right, v_right, diag_right,
// diag_scale.  Output float32.
// ---------------------------------------------------------------------------
extern "C" void kernel_launch(void* const* d_in, const int* in_sizes, int n_in,
                              void* d_out, int out_size) {
    const float* x   = (const float*)d_in[0];
    const float* ul  = (const float*)d_in[1];
    const float* vl  = (const float*)d_in[2];
    const float* dl  = (const float*)d_in[3];
    const float* ur  = (const float*)d_in[4];
    const float* vr  = (const float*)d_in[5];
    const float* dr  = (const float*)d_in[6];
    const float* dsc = (const float*)d_in[7];
    float* out = (float*)d_out;

    const int ntile = in_sizes[0] / 4096;   // 8192

    cudaFuncSetAttribute(tile_kernel, cudaFuncAttributeMaxDynamicSharedMemorySize, SMEM_SZ);

    cayley4_kernel<<<4, 512>>>(ul, vl, ur, vr);
    combine_kernel<<<2, 512>>>(dl, dr);
    tile_kernel<<<ntile / 4, 256, SMEM_SZ>>>(x, dsc, out);
}

// round 9
// speedup vs baseline: 3.0490x; 1.2357x over previous
#include <cuda_runtime.h>
#include <cuda_fp16.h>
#include <cstdint>

// ---------------------------------------------------------------------------
// Scratch (device globals; allocations are forbidden).
// ---------------------------------------------------------------------------
__device__ float g_Q[4][4096];
// Constant operand images, fp16 (single image, rounded), row-major 64x64:
//   g_mrt : Mr^T [r][j]  (B of GEMM1)
//   g_mlt : Ml^T [l][i]  (A of GEMM2)
__device__ __align__(16) __half g_mrt[4096];
__device__ __align__(16) __half g_mlt[4096];

// ---------------------------------------------------------------------------
// Helpers
// ---------------------------------------------------------------------------
__device__ __forceinline__ void ffma2p(unsigned long long& d,
                                       unsigned long long a,
                                       unsigned long long b) {
    asm("fma.rn.f32x2 %0, %1, %2, %0;" : "+l"(d) : "l"(a), "l"(b));
}
__device__ __forceinline__ unsigned long long dup2(float v) {
    unsigned long long r;
    asm("mov.b64 %0, {%1, %1};" : "=l"(r) : "r"(__float_as_uint(v)));
    return r;
}
__device__ __forceinline__ uint32_t h2_bits(__half2 h) {
    return *reinterpret_cast<uint32_t*>(&h);
}

// mma.sync m16n8k16 fp16 -> f32 (baseline PTX, legal at sm_103).
__device__ __forceinline__ void mma_f16(float c[4], const uint32_t a[4],
                                        uint32_t b0, uint32_t b1) {
    asm volatile(
        "mma.sync.aligned.m16n8k16.row.col.f32.f16.f16.f32 "
        "{%0,%1,%2,%3}, {%4,%5,%6,%7}, {%8,%9}, {%0,%1,%2,%3};"
        : "+f"(c[0]), "+f"(c[1]), "+f"(c[2]), "+f"(c[3])
        : "r"(a[0]), "r"(a[1]), "r"(a[2]), "r"(a[3]), "r"(b0), "r"(b1));
}

// ---------------------------------------------------------------------------
// In-block 64^3 GEMM, 512 threads, 2x4 blocking with packed FFMA2.
// ---------------------------------------------------------------------------
__device__ __forceinline__ void gemm64p(float* __restrict__ D,
                                        const float* __restrict__ A,
                                        const float* __restrict__ Bm, int tid) {
    const int i0 = (tid >> 4) * 2, j0 = (tid & 15) * 4;
    unsigned long long acc[2][2] = {{0ull, 0ull}, {0ull, 0ull}};
    #pragma unroll 4
    for (int k = 0; k < 64; k++) {
        ulonglong2 b = *(const ulonglong2*)(Bm + k * 64 + j0);
        unsigned long long a0 = dup2(A[(i0 + 0) * 64 + k]);
        unsigned long long a1 = dup2(A[(i0 + 1) * 64 + k]);
        ffma2p(acc[0][0], a0, b.x); ffma2p(acc[0][1], a0, b.y);
        ffma2p(acc[1][0], a1, b.x); ffma2p(acc[1][1], a1, b.y);
    }
    #pragma unroll
    for (int p = 0; p < 2; p++) {
        ulonglong2 o; o.x = acc[p][0]; o.y = acc[p][1];
        *(ulonglong2*)(D + (i0 + p) * 64 + j0) = o;
    }
}

// ---------------------------------------------------------------------------
// Kernel A: cayley via truncated product: Q = (I+B)^2 (I+B^2)(I+B^4),
// covers B^0..B^7 exactly; trunc err ~||B||^8 ~ 3e-7.  4 GEMMs.
// ---------------------------------------------------------------------------
__global__ void __launch_bounds__(512)
cayley4_kernel(const float* __restrict__ ul, const float* __restrict__ vl,
               const float* __restrict__ ur, const float* __restrict__ vr) {
    __shared__ float b0[4096], b1[4096], b2[4096];
    const float* src = (blockIdx.x == 0) ? ul : (blockIdx.x == 1) ? vl
                     : (blockIdx.x == 2) ? ur : vr;
    const int tid = threadIdx.x;

    for (int e = tid; e < 4096; e += 512) {
        int i = e >> 6, j = e & 63;
        float a = 0.0f;
        if (i > j)      a =  src[i * 64 + j];
        else if (i < j) a = -src[j * 64 + i];
        b0[e] = 0.5f * a;                         // B
    }
    __syncthreads();
    gemm64p(b1, b0, b0, tid);                     // b1 = B^2
    __syncthreads();
    for (int e = tid; e < 4096; e += 512) {
        int i = e >> 6, j = e & 63;
        b2[e] = ((i == j) ? 1.0f : 0.0f) + 2.0f * b0[e] + b1[e];   // P = (I+B)^2
    }
    __syncthreads();
    gemm64p(b0, b2, b1, tid); __syncthreads();    // b0 = P*B^2
    for (int e = tid; e < 4096; e += 512) b2[e] += b0[e];          // P *= (I+B^2)
    __syncthreads();
    gemm64p(b0, b1, b1, tid); __syncthreads();    // b0 = B^4
    gemm64p(b1, b2, b0, tid); __syncthreads();    // b1 = P*B^4
    for (int e = tid; e < 4096; e += 512) g_Q[blockIdx.x][e] = b2[e] + b1[e];
}

// ---------------------------------------------------------------------------
// Kernel B: m = Qu @ (diag * Qv); emit transposed fp16 images.
// ---------------------------------------------------------------------------
__global__ void __launch_bounds__(512)
combine_kernel(const float* __restrict__ dl, const float* __restrict__ dr) {
    __shared__ float Qu[4096], Wv[4096], D[4096];
    const int b = blockIdx.x;
    const float* qu = g_Q[b * 2 + 0];
    const float* qv = g_Q[b * 2 + 1];
    const float* dg = b ? dr : dl;
    const int tid = threadIdx.x;

    for (int e = tid; e < 4096; e += 512) {
        Qu[e] = qu[e];
        Wv[e] = dg[e >> 6] * qv[e];
    }
    __syncthreads();
    gemm64p(D, Qu, Wv, tid);
    __syncthreads();

    __half* im = b ? g_mrt : g_mlt;
    for (int e = tid; e < 4096; e += 512) {
        int t = e >> 6, s = e & 63;               // out[t][s] = D[s][t]
        im[e] = __float2half_rn(D[s * 64 + t]);
    }
}

// ---------------------------------------------------------------------------
// Kernel C: mma.sync fp16 path.  CTA = 8 warps, 4 tiles in 2 passes.
// Warp w: tile tt = w>>2, n-slab s = w&3 (r in [16s, 16s+16)).
//   GEMM1: C1 = (Xh + Xl) * Mrh     (2 chains; constant rounded to fp16)
//   GEMM2: O  = Mlh * (C1h + C1l)   (2 chains)
// Error ~2^-12 per GEMM (constant rounding only); data carried to 2^-22.
// Rows padded to 72 fp16.
// ---------------------------------------------------------------------------
#define PADB   144                 // bytes per 64-fp16 row (72 fp16)
#define MATB   (64 * PADB)         // 9216
#define MRT_H  0
#define MLT_H  (MATB)
#define XBASE  (2 * MATB)          // X: tile tt -> XBASE + tt*2*MATB (+MATB lo)
#define C1BASE (6 * MATB)          // C1: tile tt -> C1BASE + tt*2*MATB (+MATB lo)
#define SMEM_SZ (10 * MATB)        // 92160

__global__ void __launch_bounds__(256, 2)
tile_kernel(const float* __restrict__ x,
            const float* __restrict__ dsc,
            float* __restrict__ out) {
    extern __shared__ char sm[];
    const int tid = threadIdx.x;
    const int wid = tid >> 5, lane = tid & 31;
    const int g = lane >> 2, tg = lane & 3;
    const int tt = wid >> 2, s = wid & 3;

    // Constants -> smem with pad re-stride.
    // Each matrix: 4096 fp16 = 2048 u32 words; 32 words per 64-fp16 row,
    // re-strided to 36 words (PADB).  (Round-7 bug: bound was 1024 -> half
    // of each constant matrix left uninitialized -> NaN.)
    for (int q = tid; q < 2048; q += 256) {
        const int row = q >> 5, cw = q & 31;
        const int d = row * 36 + cw;
        ((uint32_t*)(sm + MRT_H))[d] = ((const uint32_t*)g_mrt)[q];
        ((uint32_t*)(sm + MLT_H))[d] = ((const uint32_t*)g_mlt)[q];
    }

    float4 dreg[4];
    #pragma unroll
    for (int v = 0; v < 4; v++) dreg[v] = ((const float4*)dsc)[v * 256 + tid];

    const int xhi = XBASE + tt * 2 * MATB, xlo = xhi + MATB;
    const int chi = C1BASE + tt * 2 * MATB, clo = chi + MATB;
    const int aoff = g * PADB + tg * 4;

    for (int pass = 0; pass < 2; pass++) {
        const size_t pbase = ((size_t)blockIdx.x * 4 + pass * 2) * 4096;
        __syncthreads();   // X/C1 buffers free from previous pass

        // Stage both tiles' X: scale, fp16 split hi/lo, padded row-major.
        #pragma unroll
        for (int st = 0; st < 2; st++) {
            const int xh = XBASE + st * 2 * MATB, xl = xh + MATB;
            const float4* xt = (const float4*)(x + pbase + st * 4096);
            #pragma unroll
            for (int v = 0; v < 4; v++) {
                const int idx = v * 256 + tid;
                float4 xv = xt[idx];
                const float4 dv = dreg[v];
                float s0 = xv.x * dv.x, s1 = xv.y * dv.y;
                float s2 = xv.z * dv.z, s3 = xv.w * dv.w;
                __half2 h01 = __floats2half2_rn(s0, s1);
                __half2 h23 = __floats2half2_rn(s2, s3);
                float2 b01 = __half22float2(h01);
                float2 b23 = __half22float2(h23);
                __half2 l01 = __floats2half2_rn(s0 - b01.x, s1 - b01.y);
                __half2 l23 = __floats2half2_rn(s2 - b23.x, s3 - b23.y);
                const int e = idx * 4, i = e >> 6, j = e & 63;
                const int ob = i * PADB + j * 2;
                *(uint2*)(sm + xh + ob) = make_uint2(h2_bits(h01), h2_bits(h23));
                *(uint2*)(sm + xl + ob) = make_uint2(h2_bits(l01), h2_bits(l23));
            }
        }
        __syncthreads();

        // ---- GEMM1: C1[i][r] = sum_j (Xh+Xl)[i][j] * Mrh[j][r] ----
        float acc1[2][4][4] = {};
        #pragma unroll
        for (int kt = 0; kt < 4; kt++) {
            const int kb = kt * 32;
            uint32_t bh0[2], bh1[2];
            #pragma unroll
            for (int nt = 0; nt < 2; nt++) {
                const int br = (s * 16 + nt * 8 + g) * PADB + tg * 4 + kb;
                bh0[nt] = *(const uint32_t*)(sm + MRT_H + br);
                bh1[nt] = *(const uint32_t*)(sm + MRT_H + br + 16);
            }
            #pragma unroll
            for (int mt = 0; mt < 4; mt++) {
                const int ab = mt * 16 * PADB + aoff + kb;
                uint32_t ah[4] = {
                    *(const uint32_t*)(sm + xhi + ab),
                    *(const uint32_t*)(sm + xhi + ab + 8 * PADB),
                    *(const uint32_t*)(sm + xhi + ab + 16),
                    *(const uint32_t*)(sm + xhi + ab + 8 * PADB + 16) };
                uint32_t al[4] = {
                    *(const uint32_t*)(sm + xlo + ab),
                    *(const uint32_t*)(sm + xlo + ab + 8 * PADB),
                    *(const uint32_t*)(sm + xlo + ab + 16),
                    *(const uint32_t*)(sm + xlo + ab + 8 * PADB + 16) };
                #pragma unroll
                for (int nt = 0; nt < 2; nt++) {
                    mma_f16(acc1[nt][mt], ah, bh0[nt], bh1[nt]);
                    mma_f16(acc1[nt][mt], al, bh0[nt], bh1[nt]);
                }
            }
        }

        // Restage C1^T rows (warp-private r in [16s, 16s+16)), fp16 split.
        #pragma unroll
        for (int nt = 0; nt < 2; nt++) {
            #pragma unroll
            for (int mt = 0; mt < 4; mt++) {
                #pragma unroll
                for (int q = 0; q < 4; q++) {
                    const int rr = s * 16 + nt * 8 + tg * 2 + (q & 1);
                    const int ii = mt * 16 + g + (q >> 1) * 8;
                    const float v = acc1[nt][mt][q];
                    __half h = __float2half_rn(v);
                    const int ob = rr * PADB + ii * 2;
                    *(__half*)(sm + chi + ob) = h;
                    *(__half*)(sm + clo + ob) = __float2half_rn(v - __half2float(h));
                }
            }
        }
        __syncwarp();

        // ---- GEMM2: O[l][r] = sum_i Mlh[l][i] * (C1h+C1l)[i][r] ----
        float acc2[2][4][4] = {};
        #pragma unroll
        for (int kt = 0; kt < 4; kt++) {
            const int kb = kt * 32;
            uint32_t ch0[2], ch1[2], cl0[2], cl1[2];
            #pragma unroll
            for (int nt = 0; nt < 2; nt++) {
                const int br = (s * 16 + nt * 8 + g) * PADB + tg * 4 + kb;
                ch0[nt] = *(const uint32_t*)(sm + chi + br);
                ch1[nt] = *(const uint32_t*)(sm + chi + br + 16);
                cl0[nt] = *(const uint32_t*)(sm + clo + br);
                cl1[nt] = *(const uint32_t*)(sm + clo + br + 16);
            }
            #pragma unroll
            for (int mt = 0; mt < 4; mt++) {
                const int ab = mt * 16 * PADB + aoff + kb;
                uint32_t am[4] = {
                    *(const uint32_t*)(sm + MLT_H + ab),
                    *(const uint32_t*)(sm + MLT_H + ab + 8 * PADB),
                    *(const uint32_t*)(sm + MLT_H + ab + 16),
                    *(const uint32_t*)(sm + MLT_H + ab + 8 * PADB + 16) };
                #pragma unroll
                for (int nt = 0; nt < 2; nt++) {
                    mma_f16(acc2[nt][mt], am, ch0[nt], ch1[nt]);
                    mma_f16(acc2[nt][mt], am, cl0[nt], cl1[nt]);
                }
            }
        }

        // Store O.
        {
            float* ob = out + pbase + tt * 4096;
            #pragma unroll
            for (int nt = 0; nt < 2; nt++) {
                const int r0 = s * 16 + nt * 8 + tg * 2;
                #pragma unroll
                for (int mt = 0; mt < 4; mt++) {
                    const int l0 = mt * 16 + g;
                    *(float2*)(ob + l0 * 64 + r0) =
                        make_float2(acc2[nt][mt][0], acc2[nt][mt][1]);
                    *(float2*)(ob + (l0 + 8) * 64 + r0) =
                        make_float2(acc2[nt][mt][2], acc2[nt][mt][3]);
                }
            }
        }
    }
}

// ---------------------------------------------------------------------------
// Launch.  Inputs: x, u_left, v_left, diag_left, u_right, v_right, diag_right,
// diag_scale.  Output float32.
// ---------------------------------------------------------------------------
extern "C" void kernel_launch(void* const* d_in, const int* in_sizes, int n_in,
                              void* d_out, int out_size) {
    const float* x   = (const float*)d_in[0];
    const float* ul  = (const float*)d_in[1];
    const float* vl  = (const float*)d_in[2];
    const float* dl  = (const float*)d_in[3];
    const float* ur  = (const float*)d_in[4];
    const float* vr  = (const float*)d_in[5];
    const float* dr  = (const float*)d_in[6];
    const float* dsc = (const float*)d_in[7];
    float* out = (float*)d_out;

    const int ntile = in_sizes[0] / 4096;   // 8192

    cudaFuncSetAttribute(tile_kernel, cudaFuncAttributeMaxDynamicSharedMemorySize, SMEM_SZ);

    cayley4_kernel<<<4, 512>>>(ul, vl, ur, vr);
    combine_kernel<<<2, 512>>>(dl, dr);
    tile_kernel<<<ntile / 4, 256, SMEM_SZ>>>(x, dsc, out);
}

// round 12
// speedup vs baseline: 3.7284x; 1.2228x over previous
#include <cuda_runtime.h>
#include <cuda_fp16.h>
#include <cstdint>

// ---------------------------------------------------------------------------
// Scratch (device globals; allocations are forbidden).
// ---------------------------------------------------------------------------
__device__ float g_Q[4][4096];
// Constant operand images, fp16, row-major 64x64:
//   g_mrt : Mr^T [r][j]  (B of GEMM1)
//   g_mlt : Ml^T [l][i]  (A of GEMM2)
__device__ __align__(16) __half g_mrt[4096];
__device__ __align__(16) __half g_mlt[4096];

// ---------------------------------------------------------------------------
// Helpers
// ---------------------------------------------------------------------------
__device__ __forceinline__ void ffma2p(unsigned long long& d,
                                       unsigned long long a,
                                       unsigned long long b) {
    asm("fma.rn.f32x2 %0, %1, %2, %0;" : "+l"(d) : "l"(a), "l"(b));
}
__device__ __forceinline__ unsigned long long dup2(float v) {
    unsigned long long r;
    asm("mov.b64 %0, {%1, %1};" : "=l"(r) : "r"(__float_as_uint(v)));
    return r;
}
__device__ __forceinline__ uint32_t h2_bits(__half2 h) {
    return *reinterpret_cast<uint32_t*>(&h);
}

// mma.sync m16n8k16 fp16 -> f32 (baseline PTX, legal at sm_103).
__device__ __forceinline__ void mma_f16(float c[4], const uint32_t a[4],
                                        uint32_t b0, uint32_t b1) {
    asm volatile(
        "mma.sync.aligned.m16n8k16.row.col.f32.f16.f16.f32 "
        "{%0,%1,%2,%3}, {%4,%5,%6,%7}, {%8,%9}, {%0,%1,%2,%3};"
        : "+f"(c[0]), "+f"(c[1]), "+f"(c[2]), "+f"(c[3])
        : "r"(a[0]), "r"(a[1]), "r"(a[2]), "r"(a[3]), "r"(b0), "r"(b1));
}

// ---------------------------------------------------------------------------
// In-block 64^3 GEMM, 512 threads, 2x4 blocking with packed FFMA2.
// ---------------------------------------------------------------------------
__device__ __forceinline__ void gemm64p(float* __restrict__ D,
                                        const float* __restrict__ A,
                                        const float* __restrict__ Bm, int tid) {
    const int i0 = (tid >> 4) * 2, j0 = (tid & 15) * 4;
    unsigned long long acc[2][2] = {{0ull, 0ull}, {0ull, 0ull}};
    #pragma unroll 4
    for (int k = 0; k < 64; k++) {
        ulonglong2 b = *(const ulonglong2*)(Bm + k * 64 + j0);
        unsigned long long a0 = dup2(A[(i0 + 0) * 64 + k]);
        unsigned long long a1 = dup2(A[(i0 + 1) * 64 + k]);
        ffma2p(acc[0][0], a0, b.x); ffma2p(acc[0][1], a0, b.y);
        ffma2p(acc[1][0], a1, b.x); ffma2p(acc[1][1], a1, b.y);
    }
    #pragma unroll
    for (int p = 0; p < 2; p++) {
        ulonglong2 o; o.x = acc[p][0]; o.y = acc[p][1];
        *(ulonglong2*)(D + (i0 + p) * 64 + j0) = o;
    }
}

// ---------------------------------------------------------------------------
// Kernel A: cayley via truncated product: Q = (I+B)^2 (I+B^2)(I+B^4),
// covers B^0..B^7 exactly; trunc err ~||B||^8 ~ 4e-7.  4 GEMMs.
// ---------------------------------------------------------------------------
__global__ void __launch_bounds__(512)
cayley4_kernel(const float* __restrict__ ul, const float* __restrict__ vl,
               const float* __restrict__ ur, const float* __restrict__ vr) {
    __shared__ float b0[4096], b1[4096], b2[4096];
    const float* src = (blockIdx.x == 0) ? ul : (blockIdx.x == 1) ? vl
                     : (blockIdx.x == 2) ? ur : vr;
    const int tid = threadIdx.x;

    for (int e = tid; e < 4096; e += 512) {
        int i = e >> 6, j = e & 63;
        float a = 0.0f;
        if (i > j)      a =  src[i * 64 + j];
        else if (i < j) a = -src[j * 64 + i];
        b0[e] = 0.5f * a;                         // B
    }
    __syncthreads();
    gemm64p(b1, b0, b0, tid);                     // b1 = B^2
    __syncthreads();
    for (int e = tid; e < 4096; e += 512) {
        int i = e >> 6, j = e & 63;
        b2[e] = ((i == j) ? 1.0f : 0.0f) + 2.0f * b0[e] + b1[e];   // P = (I+B)^2
    }
    __syncthreads();
    gemm64p(b0, b2, b1, tid); __syncthreads();    // b0 = P*B^2
    for (int e = tid; e < 4096; e += 512) b2[e] += b0[e];          // P *= (I+B^2)
    __syncthreads();
    gemm64p(b0, b1, b1, tid); __syncthreads();    // b0 = B^4
    gemm64p(b1, b2, b0, tid); __syncthreads();    // b1 = P*B^4
    for (int e = tid; e < 4096; e += 512) g_Q[blockIdx.x][e] = b2[e] + b1[e];
}

// ---------------------------------------------------------------------------
// Kernel B: m = Qu @ (diag * Qv); emit transposed fp16 images.
// ---------------------------------------------------------------------------
__global__ void __launch_bounds__(512)
combine_kernel(const float* __restrict__ dl, const float* __restrict__ dr) {
    __shared__ float Qu[4096], Wv[4096], D[4096];
    const int b = blockIdx.x;
    const float* qu = g_Q[b * 2 + 0];
    const float* qv = g_Q[b * 2 + 1];
    const float* dg = b ? dr : dl;
    const int tid = threadIdx.x;

    for (int e = tid; e < 4096; e += 512) {
        Qu[e] = qu[e];
        Wv[e] = dg[e >> 6] * qv[e];
    }
    __syncthreads();
    gemm64p(D, Qu, Wv, tid);
    __syncthreads();

    __half* im = b ? g_mrt : g_mlt;
    for (int e = tid; e < 4096; e += 512) {
        int t = e >> 6, s = e & 63;               // out[t][s] = D[s][t]
        im[e] = __float2half_rn(D[s * 64 + t]);
    }
}

// ---------------------------------------------------------------------------
// Kernel C: pure-fp16 mma.sync path.  CTA = 8 warps, 4 tiles in 2 passes.
// Warp w: tile tt = w>>2, n-slab s = w&3 (r in [16s, 16s+16)).
//   GEMM1: C1 = Xh * Mrh    (1 chain)
//   GEMM2: O  = Mlh * C1h   (1 chain)
// fp32 accumulate; error = 4 fp16-rounded operand images ~ 2.8e-4 RMS
// (calibrated: 2 images measured 1.97e-4).  Rows padded to 72 fp16.
// ---------------------------------------------------------------------------
#define PADB   144                 // bytes per 64-fp16 row (72 fp16)
#define MATB   (64 * PADB)         // 9216
#define MRT_H  0
#define MLT_H  (MATB)
#define XBASE  (2 * MATB)          // X: staged tile st -> XBASE + st*MATB
#define C1BASE (4 * MATB)          // C1: staged tile st -> C1BASE + st*MATB
#define SMEM_SZ (6 * MATB)         // 55296

__global__ void __launch_bounds__(256, 3)
tile_kernel(const float* __restrict__ x,
            const float* __restrict__ dsc,
            float* __restrict__ out) {
    extern __shared__ char sm[];
    const int tid = threadIdx.x;
    const int wid = tid >> 5, lane = tid & 31;
    const int g = lane >> 2, tg = lane & 3;
    const int tt = wid >> 2, s = wid & 3;

    // Constants -> smem with pad re-stride.
    // Each matrix: 4096 fp16 = 2048 u32 words; 32 words per 64-fp16 row,
    // re-strided to 36 words (PADB).
    for (int q = tid; q < 2048; q += 256) {
        const int row = q >> 5, cw = q & 31;
        const int d = row * 36 + cw;
        ((uint32_t*)(sm + MRT_H))[d] = ((const uint32_t*)g_mrt)[q];
        ((uint32_t*)(sm + MLT_H))[d] = ((const uint32_t*)g_mlt)[q];
    }

    float4 dreg[4];
    #pragma unroll
    for (int v = 0; v < 4; v++) dreg[v] = ((const float4*)dsc)[v * 256 + tid];

    const int xhi = XBASE + tt * MATB;
    const int chi = C1BASE + tt * MATB;
    const int aoff = g * PADB + tg * 4;

    for (int pass = 0; pass < 2; pass++) {
        const size_t pbase = ((size_t)blockIdx.x * 4 + pass * 2) * 4096;
        __syncthreads();   // X/C1 buffers free from previous pass

        // Stage both tiles' X: scale, round to fp16, padded row-major.
        #pragma unroll
        for (int st = 0; st < 2; st++) {
            const int xh = XBASE + st * MATB;
            const float4* xt = (const float4*)(x + pbase + st * 4096);
            #pragma unroll
            for (int v = 0; v < 4; v++) {
                const int idx = v * 256 + tid;
                float4 xv = xt[idx];
                const float4 dv = dreg[v];
                __half2 h01 = __floats2half2_rn(xv.x * dv.x, xv.y * dv.y);
                __half2 h23 = __floats2half2_rn(xv.z * dv.z, xv.w * dv.w);
                const int e = idx * 4, i = e >> 6, j = e & 63;
                *(uint2*)(sm + xh + i * PADB + j * 2) =
                    make_uint2(h2_bits(h01), h2_bits(h23));
            }
        }
        __syncthreads();

        // ---- GEMM1: C1[i][r] = sum_j Xh[i][j] * Mrh[j][r] ----
        float acc1[2][4][4] = {};
        #pragma unroll
        for (int kt = 0; kt < 4; kt++) {
            const int kb = kt * 32;
            uint32_t bh0[2], bh1[2];
            #pragma unroll
            for (int nt = 0; nt < 2; nt++) {
                const int br = (s * 16 + nt * 8 + g) * PADB + tg * 4 + kb;
                bh0[nt] = *(const uint32_t*)(sm + MRT_H + br);
                bh1[nt] = *(const uint32_t*)(sm + MRT_H + br + 16);
            }
            #pragma unroll
            for (int mt = 0; mt < 4; mt++) {
                const int ab = mt * 16 * PADB + aoff + kb;
                uint32_t ah[4] = {
                    *(const uint32_t*)(sm + xhi + ab),
                    *(const uint32_t*)(sm + xhi + ab + 8 * PADB),
                    *(const uint32_t*)(sm + xhi + ab + 16),
                    *(const uint32_t*)(sm + xhi + ab + 8 * PADB + 16) };
                #pragma unroll
                for (int nt = 0; nt < 2; nt++)
                    mma_f16(acc1[nt][mt], ah, bh0[nt], bh1[nt]);
            }
        }

        // Restage C1^T rows (warp-private r in [16s, 16s+16)), fp16.
        #pragma unroll
        for (int nt = 0; nt < 2; nt++) {
            #pragma unroll
            for (int mt = 0; mt < 4; mt++) {
                #pragma unroll
                for (int q = 0; q < 4; q++) {
                    const int rr = s * 16 + nt * 8 + tg * 2 + (q & 1);
                    const int ii = mt * 16 + g + (q >> 1) * 8;
                    *(__half*)(sm + chi + rr * PADB + ii * 2) =
                        __float2half_rn(acc1[nt][mt][q]);
                }
            }
        }
        __syncwarp();

        // ---- GEMM2: O[l][r] = sum_i Mlh[l][i] * C1h[i][r] ----
        float acc2[2][4][4] = {};
        #pragma unroll
        for (int kt = 0; kt < 4; kt++) {
            const int kb = kt * 32;
            uint32_t ch0[2], ch1[2];
            #pragma unroll
            for (int nt = 0; nt < 2; nt++) {
                const int br = (s * 16 + nt * 8 + g) * PADB + tg * 4 + kb;
                ch0[nt] = *(const uint32_t*)(sm + chi + br);
                ch1[nt] = *(const uint32_t*)(sm + chi + br + 16);
            }
            #pragma unroll
            for (int mt = 0; mt < 4; mt++) {
                const int ab = mt * 16 * PADB + aoff + kb;
                uint32_t am[4] = {
                    *(const uint32_t*)(sm + MLT_H + ab),
                    *(const uint32_t*)(sm + MLT_H + ab + 8 * PADB),
                    *(const uint32_t*)(sm + MLT_H + ab + 16),
                    *(const uint32_t*)(sm + MLT_H + ab + 8 * PADB + 16) };
                #pragma unroll
                for (int nt = 0; nt < 2; nt++)
                    mma_f16(acc2[nt][mt], am, ch0[nt], ch1[nt]);
            }
        }

        // Store O.
        {
            float* ob = out + pbase + tt * 4096;
            #pragma unroll
            for (int nt = 0; nt < 2; nt++) {
                const int r0 = s * 16 + nt * 8 + tg * 2;
                #pragma unroll
                for (int mt = 0; mt < 4; mt++) {
                    const int l0 = mt * 16 + g;
                    *(float2*)(ob + l0 * 64 + r0) =
                        make_float2(acc2[nt][mt][0], acc2[nt][mt][1]);
                    *(float2*)(ob + (l0 + 8) * 64 + r0) =
                        make_float2(acc2[nt][mt][2], acc2[nt][mt][3]);
                }
            }
        }
    }
}

// ---------------------------------------------------------------------------
// Launch.  Inputs: x, u_left, v_left, diag_left, u_right, v_right, diag_right,
// diag_scale.  Output float32.
// ---------------------------------------------------------------------------
extern "C" void kernel_launch(void* const* d_in, const int* in_sizes, int n_in,
                              void* d_out, int out_size) {
    const float* x   = (const float*)d_in[0];
    const float* ul  = (const float*)d_in[1];
    const float* vl  = (const float*)d_in[2];
    const float* dl  = (const float*)d_in[3];
    const float* ur  = (const float*)d_in[4];
    const float* vr  = (const float*)d_in[5];
    const float* dr  = (const float*)d_in[6];
    const float* dsc = (const float*)d_in[7];
    float* out = (float*)d_out;

    const int ntile = in_sizes[0] / 4096;   // 8192

    cudaFuncSetAttribute(tile_kernel, cudaFuncAttributeMaxDynamicSharedMemorySize, SMEM_SZ);

    cayley4_kernel<<<4, 512>>>(ul, vl, ur, vr);
    combine_kernel<<<2, 512>>>(dl, dr);
    tile_kernel<<<ntile / 4, 256, SMEM_SZ>>>(x, dsc, out);
}

// round 15
// speedup vs baseline: 4.1001x; 1.0997x over previous
#include <cuda_runtime.h>
#include <cuda_fp16.h>
#include <cstdint>

// ---------------------------------------------------------------------------
// Scratch (device globals; allocations are forbidden).
// ---------------------------------------------------------------------------
__device__ float g_Q[4][4096];
// Constant operand images, fp16, row-major 64x64:
//   g_mrt : Mr^T [r][j]  (A of GEMM1')
//   g_mlt : Ml^T [l][i]  (A of GEMM2)
__device__ __align__(16) __half g_mrt[4096];
__device__ __align__(16) __half g_mlt[4096];

// ---------------------------------------------------------------------------
// Helpers
// ---------------------------------------------------------------------------
__device__ __forceinline__ void ffma2p(unsigned long long& d,
                                       unsigned long long a,
                                       unsigned long long b) {
    asm("fma.rn.f32x2 %0, %1, %2, %0;" : "+l"(d) : "l"(a), "l"(b));
}
__device__ __forceinline__ unsigned long long dup2(float v) {
    unsigned long long r;
    asm("mov.b64 %0, {%1, %1};" : "=l"(r) : "r"(__float_as_uint(v)));
    return r;
}
__device__ __forceinline__ uint32_t h2_bits(__half2 h) {
    return *reinterpret_cast<uint32_t*>(&h);
}
__device__ __forceinline__ uint32_t packh2(float a, float b) {
    __half2 h = __floats2half2_rn(a, b);
    return *reinterpret_cast<uint32_t*>(&h);
}

// mma.sync m16n8k16 fp16 -> f32 (baseline PTX, legal at sm_103).
__device__ __forceinline__ void mma_f16(float c[4], const uint32_t a[4],
                                        uint32_t b0, uint32_t b1) {
    asm volatile(
        "mma.sync.aligned.m16n8k16.row.col.f32.f16.f16.f32 "
        "{%0,%1,%2,%3}, {%4,%5,%6,%7}, {%8,%9}, {%0,%1,%2,%3};"
        : "+f"(c[0]), "+f"(c[1]), "+f"(c[2]), "+f"(c[3])
        : "r"(a[0]), "r"(a[1]), "r"(a[2]), "r"(a[3]), "r"(b0), "r"(b1));
}

// ---------------------------------------------------------------------------
// In-block 64^3 GEMM, 256 threads, 4x4 blocking with packed FFMA2.
// (0.5 FMA/B of smem traffic, B rows broadcast-dedup across i-groups.)
// ---------------------------------------------------------------------------
__device__ __forceinline__ void gemm64q(float* __restrict__ D,
                                        const float* __restrict__ A,
                                        const float* __restrict__ Bm, int tid) {
    const int i0 = (tid >> 4) * 4, j0 = (tid & 15) * 4;
    unsigned long long acc[4][2] = {};
    #pragma unroll 4
    for (int k = 0; k < 64; k++) {
        ulonglong2 b = *(const ulonglong2*)(Bm + k * 64 + j0);
        #pragma unroll
        for (int p = 0; p < 4; p++) {
            unsigned long long ap = dup2(A[(i0 + p) * 64 + k]);
            ffma2p(acc[p][0], ap, b.x); ffma2p(acc[p][1], ap, b.y);
        }
    }
    #pragma unroll
    for (int p = 0; p < 4; p++) {
        ulonglong2 o; o.x = acc[p][0]; o.y = acc[p][1];
        *(ulonglong2*)(D + (i0 + p) * 64 + j0) = o;
    }
}

// ---------------------------------------------------------------------------
// Kernel A: cayley via truncated product: Q = (I+B)^2 (I+B^2)(I+B^4),
// covers B^0..B^7 exactly; trunc err ~||B||^8 ~ 4e-7.  4 GEMMs, 256 thr.
// ---------------------------------------------------------------------------
__global__ void __launch_bounds__(256)
cayley4_kernel(const float* __restrict__ ul, const float* __restrict__ vl,
               const float* __restrict__ ur, const float* __restrict__ vr) {
    __shared__ float b0[4096], b1[4096], b2[4096];
    const float* src = (blockIdx.x == 0) ? ul : (blockIdx.x == 1) ? vl
                     : (blockIdx.x == 2) ? ur : vr;
    const int tid = threadIdx.x;

    for (int e = tid; e < 4096; e += 256) {
        int i = e >> 6, j = e & 63;
        float a = 0.0f;
        if (i > j)      a =  src[i * 64 + j];
        else if (i < j) a = -src[j * 64 + i];
        b0[e] = 0.5f * a;                         // B
    }
    __syncthreads();
    gemm64q(b1, b0, b0, tid);                     // b1 = B^2
    __syncthreads();
    for (int e = tid; e < 4096; e += 256) {
        int i = e >> 6, j = e & 63;
        b2[e] = ((i == j) ? 1.0f : 0.0f) + 2.0f * b0[e] + b1[e];   // P = (I+B)^2
    }
    __syncthreads();
    gemm64q(b0, b2, b1, tid); __syncthreads();    // b0 = P*B^2
    for (int e = tid; e < 4096; e += 256) b2[e] += b0[e];          // P *= (I+B^2)
    __syncthreads();
    gemm64q(b0, b1, b1, tid); __syncthreads();    // b0 = B^4
    gemm64q(b1, b2, b0, tid); __syncthreads();    // b1 = P*B^4
    for (int e = tid; e < 4096; e += 256) g_Q[blockIdx.x][e] = b2[e] + b1[e];
}

// ---------------------------------------------------------------------------
// Kernel B: m = Qu @ (diag * Qv); emit transposed fp16 images.
// ---------------------------------------------------------------------------
__global__ void __launch_bounds__(256)
combine_kernel(const float* __restrict__ dl, const float* __restrict__ dr) {
    __shared__ float Qu[4096], Wv[4096], D[4096];
    const int b = blockIdx.x;
    const float* qu = g_Q[b * 2 + 0];
    const float* qv = g_Q[b * 2 + 1];
    const float* dg = b ? dr : dl;
    const int tid = threadIdx.x;

    for (int e = tid; e < 4096; e += 256) {
        Qu[e] = qu[e];
        Wv[e] = dg[e >> 6] * qv[e];
    }
    __syncthreads();
    gemm64q(D, Qu, Wv, tid);
    __syncthreads();

    __half* im = b ? g_mrt : g_mlt;
    for (int e = tid; e < 4096; e += 256) {
        int t = e >> 6, s = e & 63;               // out[t][s] = D[s][t]
        im[e] = __float2half_rn(D[s * 64 + t]);
    }
}

// ---------------------------------------------------------------------------
// Kernel C: pure-fp16 mma.sync, register-chained.  CTA = 8 warps, 4 tiles
// in 2 passes.  Warp w: tile tt = w>>2, r-slab s = w&3 (r in [16s,16s+16)).
//
//   GEMM1': C1T = Mrt(A, m=r) x X(B, n=i, col-major-k = X row-major)
//           -> C-frag (r=g, i=2tg) per thread.
//   pack:   __floats2half2_rn(c0,c1) IS the GEMM2 B-frag (k=i, n=r) --
//           C1 never touches smem, no transpose, no syncwarp.
//   GEMM2:  O = Mlt(A, m=l) x C1(B from regs).
//
// Numerics identical to round 12 (same _rn roundings): rel_err ~3.5e-4.
// ---------------------------------------------------------------------------
#define PADB   144                 // bytes per 64-fp16 row (72 fp16)
#define MATB   (64 * PADB)         // 9216
#define MRT_H  0
#define MLT_H  (MATB)
#define XBASE  (2 * MATB)          // X: staged tile st -> XBASE + st*MATB
#define SMEM_SZ (4 * MATB)         // 36864

__global__ void __launch_bounds__(256, 3)
tile_kernel(const float* __restrict__ x,
            const float* __restrict__ dsc,
            float* __restrict__ out) {
    extern __shared__ char sm[];
    const int tid = threadIdx.x;
    const int wid = tid >> 5, lane = tid & 31;
    const int g = lane >> 2, tg = lane & 3;
    const int tt = wid >> 2, s = wid & 3;
    const int slab = s * 16;

    // Constants -> smem with pad re-stride (2048 u32 words per matrix).
    for (int q = tid; q < 2048; q += 256) {
        const int row = q >> 5, cw = q & 31;
        const int d = row * 36 + cw;
        ((uint32_t*)(sm + MRT_H))[d] = ((const uint32_t*)g_mrt)[q];
        ((uint32_t*)(sm + MLT_H))[d] = ((const uint32_t*)g_mlt)[q];
    }

    const int xb = XBASE + tt * MATB;
    const float4* dsc4 = (const float4*)dsc;

    for (int pass = 0; pass < 2; pass++) {
        const size_t pbase = ((size_t)blockIdx.x * 4 + pass * 2) * 4096;
        __syncthreads();   // X buffers free from previous pass

        // Stage both tiles' X: scale, round to fp16, padded row-major.
        #pragma unroll
        for (int st = 0; st < 2; st++) {
            const int xh = XBASE + st * MATB;
            const float4* xt = (const float4*)(x + pbase + st * 4096);
            #pragma unroll
            for (int v = 0; v < 4; v++) {
                const int idx = v * 256 + tid;
                float4 xv = xt[idx];
                const float4 dv = dsc4[idx];
                uint32_t h01 = packh2(xv.x * dv.x, xv.y * dv.y);
                uint32_t h23 = packh2(xv.z * dv.z, xv.w * dv.w);
                const int e = idx * 4, i = e >> 6, j = e & 63;
                *(uint2*)(sm + xh + i * PADB + j * 2) = make_uint2(h01, h23);
            }
        }
        __syncthreads();

        // ---- GEMM1': C1T[r][i] = sum_j Mrt[r][j] * X[i][j] ----
        // m = r (warp slab, 1 m-tile), n = i (8 n-tiles), k = j (4 steps).
        float c1t[8][4] = {};
        #pragma unroll
        for (int kt = 0; kt < 4; kt++) {
            const int kb = kt * 32 + tg * 4;
            uint32_t am[4] = {
                *(const uint32_t*)(sm + MRT_H + (slab + g) * PADB + kb),
                *(const uint32_t*)(sm + MRT_H + (slab + 8 + g) * PADB + kb),
                *(const uint32_t*)(sm + MRT_H + (slab + g) * PADB + kb + 16),
                *(const uint32_t*)(sm + MRT_H + (slab + 8 + g) * PADB + kb + 16) };
            #pragma unroll
            for (int nt = 0; nt < 8; nt++) {
                const int bbase = xb + (8 * nt + g) * PADB + kb;
                uint32_t b0 = *(const uint32_t*)(sm + bbase);
                uint32_t b1 = *(const uint32_t*)(sm + bbase + 16);
                mma_f16(c1t[nt], am, b0, b1);
            }
        }

        // Pack C1T C-frags into GEMM2 B-frags (registers only).
        // bf[kt][nb][reg]: nb=0 -> r=slab+g (c0,c1); nb=1 -> r=slab+8+g (c2,c3).
        uint32_t bf[4][2][2];
        #pragma unroll
        for (int kt = 0; kt < 4; kt++) {
            bf[kt][0][0] = packh2(c1t[2 * kt][0],     c1t[2 * kt][1]);
            bf[kt][0][1] = packh2(c1t[2 * kt + 1][0], c1t[2 * kt + 1][1]);
            bf[kt][1][0] = packh2(c1t[2 * kt][2],     c1t[2 * kt][3]);
            bf[kt][1][1] = packh2(c1t[2 * kt + 1][2], c1t[2 * kt + 1][3]);
        }

        // ---- GEMM2: O[l][r] = sum_i Mlt[l][i] * C1[i][r] ----
        // m = l (4 m-tiles), n = r (2 blocks of 8), k = i (4 steps).
        float acc2[2][4][4] = {};
        #pragma unroll
        for (int kt = 0; kt < 4; kt++) {
            const int kb = kt * 32 + tg * 4;
            #pragma unroll
            for (int mt = 0; mt < 4; mt++) {
                uint32_t am[4] = {
                    *(const uint32_t*)(sm + MLT_H + (mt * 16 + g) * PADB + kb),
                    *(const uint32_t*)(sm + MLT_H + (mt * 16 + 8 + g) * PADB + kb),
                    *(const uint32_t*)(sm + MLT_H + (mt * 16 + g) * PADB + kb + 16),
                    *(const uint32_t*)(sm + MLT_H + (mt * 16 + 8 + g) * PADB + kb + 16) };
                #pragma unroll
                for (int nb = 0; nb < 2; nb++)
                    mma_f16(acc2[nb][mt], am, bf[kt][nb][0], bf[kt][nb][1]);
            }
        }

        // Store O: l = 16mt + g (+8), r = slab + nb*8 + 2tg (+1).
        {
            float* ob = out + pbase + tt * 4096;
            #pragma unroll
            for (int nb = 0; nb < 2; nb++) {
                const int r0 = slab + nb * 8 + tg * 2;
                #pragma unroll
                for (int mt = 0; mt < 4; mt++) {
                    const int l0 = mt * 16 + g;
                    *(float2*)(ob + l0 * 64 + r0) =
                        make_float2(acc2[nb][mt][0], acc2[nb][mt][1]);
                    *(float2*)(ob + (l0 + 8) * 64 + r0) =
                        make_float2(acc2[nb][mt][2], acc2[nb][mt][3]);
                }
            }
        }
    }
}

// ---------------------------------------------------------------------------
// Launch.  Inputs: x, u_left, v_left, diag_left, u_right, v_right, diag_right,
// diag_scale.  Output float32.
// ---------------------------------------------------------------------------
extern "C" void kernel_launch(void* const* d_in, const int* in_sizes, int n_in,
                              void* d_out, int out_size) {
    const float* x   = (const float*)d_in[0];
    const float* ul  = (const float*)d_in[1];
    const float* vl  = (const float*)d_in[2];
    const float* dl  = (const float*)d_in[3];
    const float* ur  = (const float*)d_in[4];
    const float* vr  = (const float*)d_in[5];
    const float* dr  = (const float*)d_in[6];
    const float* dsc = (const float*)d_in[7];
    float* out = (float*)d_out;

    const int ntile = in_sizes[0] / 4096;   // 8192

    cudaFuncSetAttribute(tile_kernel, cudaFuncAttributeMaxDynamicSharedMemorySize, SMEM_SZ);

    cayley4_kernel<<<4, 256>>>(ul, vl, ur, vr);
    combine_kernel<<<2, 256>>>(dl, dr);
    tile_kernel<<<ntile / 4, 256, SMEM_SZ>>>(x, dsc, out);
}